// round 11
// baseline (speedup 1.0000x reference)
#include <cuda_runtime.h>

#define BB 128
#define NT 64    // n1: templates
#define NM 128   // n2: label points

__device__ float g_gpool[BB * 32 * NM];

typedef unsigned long long ull;

__device__ __forceinline__ ull pk(float lo, float hi) {
    ull r; asm("mov.b64 %0,{%1,%2};" : "=l"(r) : "f"(lo), "f"(hi)); return r;
}
__device__ __forceinline__ ull pk1(float v) {
    ull r; asm("mov.b64 %0,{%1,%1};" : "=l"(r) : "f"(v)); return r;
}
__device__ __forceinline__ void upk(ull v, float& lo, float& hi) {
    asm("mov.b64 {%0,%1},%2;" : "=f"(lo), "=f"(hi) : "l"(v));
}
__device__ __forceinline__ ull ffma2(ull a, ull b, ull c) {
    ull d; asm("fma.rn.f32x2 %0,%1,%2,%3;" : "=l"(d) : "l"(a), "l"(b), "l"(c)); return d;
}
__device__ __forceinline__ ull fadd2(ull a, ull b) {
    ull d; asm("add.rn.f32x2 %0,%1,%2;" : "=l"(d) : "l"(a), "l"(b)); return d;
}

// ---------------------------------------------------------------------------
// Kernel 1: global-attention branch -> g_gpool (B,32,NM)
// R10 structure (286.9us total, gpool ~228) + 4 accumulator chains per
// matvec stage (even/odd c split) to double FFMA dependency ILP.
// ---------------------------------------------------------------------------
__global__ __launch_bounds__(128) void k_gpool(
    const float* __restrict__ x_label, const float* __restrict__ x_object,
    const float* __restrict__ template_xyz,
    const float* __restrict__ gw_w1, const float* __restrict__ gw_b1,
    const float* __restrict__ gw_s,  const float* __restrict__ gw_t,
    const float* __restrict__ gw_w2, const float* __restrict__ gw_b2,
    const float* __restrict__ gm_w1, const float* __restrict__ gm_s1,
    const float* __restrict__ gm_t1, const float* __restrict__ gm_w2,
    const float* __restrict__ gm_s2, const float* __restrict__ gm_t2)
{
    __shared__ float xoT[64][33];                    // [n][c] padded
    __shared__ float Bn[64][33];                     // [n][o] = -s*(W1@xo)
    __shared__ float Tn[64][33];                     // [n][o] gm1 xyz + t1
    __shared__ float As[32][33];                     // [ml][o]
    __shared__ __align__(16) float Wst[3][32][32];   // staging; bufT alias
    __shared__ __align__(16) float xls[32][32];      // staging; bufG alias
    __shared__ __align__(16) float bufL[4][32][4];   // exchange buffer L
    __shared__ float b2s[32], ct2s[32];

    const int tid = threadIdx.x;
    const int b = blockIdx.x >> 2, mt = blockIdx.x & 3;

    // ---- stage inputs + weights (coalesced) ----
    for (int i = tid; i < 2048; i += 128) {
        int c = i >> 6, n = i & 63;
        xoT[n][c] = x_object[(size_t)b * 2048 + i];
    }
    for (int i = tid; i < 1024; i += 128) {
        int c = i >> 5, ml = i & 31;
        xls[c][ml] = x_label[(size_t)b * 4096 + c * 128 + mt * 32 + ml];
    }
    for (int i = tid; i < 1024; i += 128) {
        int c = i >> 5, o = i & 31;
        Wst[0][c][o] = gw_w2[o * 32 + c];
        Wst[1][c][o] = gm_s1[o] * gm_w1[o * 35 + 3 + c];
        Wst[2][c][o] = gm_s2[o] * gm_w2[o * 32 + c];
    }
    if (tid < 32) { b2s[tid] = gw_b2[tid]; ct2s[tid] = gm_t2[tid]; }
    __syncthreads();

    // ---- per-(b,n) and per-(b,m) precompute ----
    for (int i = tid; i < 2048; i += 128) {
        int o = i >> 6, n = i & 63;
        float a = 0.f;
        #pragma unroll
        for (int c = 0; c < 32; c++) a += gw_w1[o * 32 + c] * xoT[n][c];
        Bn[n][o] = -gw_s[o] * a;
        const float* tx = template_xyz + (size_t)b * 192 + n * 3;
        Tn[n][o] = gm_s1[o] * (gm_w1[o * 35] * tx[0] + gm_w1[o * 35 + 1] * tx[1] +
                               gm_w1[o * 35 + 2] * tx[2]) + gm_t1[o];
    }
    for (int i = tid; i < 1024; i += 128) {
        int o = i >> 5, ml = i & 31;
        float a = 0.f;
        #pragma unroll
        for (int c = 0; c < 32; c++) a += gw_w1[o * 32 + c] * xls[c][ml];
        As[ml][o] = gw_s[o] * a + gw_s[o] * gw_b1[o] + gw_t[o];
    }
    __syncthreads();

    // ---- hoist weight columns into registers (const-indexed only) ----
    const int w = tid >> 5, o = tid & 31;
    float w2r[32], wm1r[32], wm2r[32];
    #pragma unroll
    for (int c = 0; c < 32; c++) {
        w2r[c]  = Wst[0][c][o];
        wm1r[c] = Wst[1][c][o];
        wm2r[c] = Wst[2][c][o];
    }
    const float bias2 = b2s[o], biasT = ct2s[o];
    __syncthreads();   // Wst and xls become exchange buffers from here on

    // exchange buffer views (per warp: 32 lanes x 4 floats = 128 floats)
    float* bufGp = &xls[0][0];
    float* bufTp = &Wst[0][0][0];
    float4* mbL = (float4*)&bufL[w][o][0];
    float4* mbG = (float4*)(bufGp + (w * 32 + o) * 4);
    float4* mbT = (float4*)(bufTp + (w * 32 + o) * 4);
    const ulonglong2* bvL = (const ulonglong2*)&bufL[w][0][0];
    const ulonglong2* bvG = (const ulonglong2*)(bufGp + w * 128);
    const ulonglong2* bvT = (const ulonglong2*)(bufTp + w * 128);

    #pragma unroll 1
    for (int mi = 0; mi < 8; mi++) {
        const int ml = w * 8 + mi;
        const float as = As[ml][o];
        float um = 0.f;

        #pragma unroll 1
        for (int j = 0; j < 16; j++) {
            const int n0 = 4 * j;

            // stage gw1 (folded): leaky(as + Bn[n][o]) -> bufL
            float z0 = as + Bn[n0 + 0][o];
            float z1 = as + Bn[n0 + 1][o];
            float z2 = as + Bn[n0 + 2][o];
            float z3 = as + Bn[n0 + 3][o];
            *mbL = make_float4(fmaxf(z0, 0.2f * z0), fmaxf(z1, 0.2f * z1),
                               fmaxf(z2, 0.2f * z2), fmaxf(z3, 0.2f * z3));
            __syncwarp();

            // stage gw2: q = b2 + W2 @ L  (4 accumulator chains)
            ull q01a = pk1(bias2), q23a = q01a;
            ull q01b = 0ULL, q23b = 0ULL;
            #pragma unroll
            for (int c = 0; c < 32; c += 2) {
                ull wpa = pk1(w2r[c]);
                ulonglong2 va = bvL[c];
                q01a = ffma2(va.x, wpa, q01a);
                q23a = ffma2(va.y, wpa, q23a);
                ull wpb = pk1(w2r[c + 1]);
                ulonglong2 vb = bvL[c + 1];
                q01b = ffma2(vb.x, wpb, q01b);
                q23b = ffma2(vb.y, wpb, q23b);
            }
            ull q01 = fadd2(q01a, q01b), q23 = fadd2(q23a, q23b);

            // gate: g = sigmoid(q) * xo[n][o] -> bufG
            float q0, q1, q2, q3;
            upk(q01, q0, q1); upk(q23, q2, q3);
            float g0 = __fdividef(xoT[n0 + 0][o], 1.f + __expf(-q0));
            float g1 = __fdividef(xoT[n0 + 1][o], 1.f + __expf(-q1));
            float g2 = __fdividef(xoT[n0 + 2][o], 1.f + __expf(-q2));
            float g3 = __fdividef(xoT[n0 + 3][o], 1.f + __expf(-q3));
            *mbG = make_float4(g0, g1, g2, g3);
            __syncwarp();

            // stage gm1: t = Tn + Wm1 @ g, relu -> bufT (4 chains)
            ull t01a = pk(Tn[n0 + 0][o], Tn[n0 + 1][o]);
            ull t23a = pk(Tn[n0 + 2][o], Tn[n0 + 3][o]);
            ull t01b = 0ULL, t23b = 0ULL;
            #pragma unroll
            for (int c = 0; c < 32; c += 2) {
                ull wpa = pk1(wm1r[c]);
                ulonglong2 va = bvG[c];
                t01a = ffma2(va.x, wpa, t01a);
                t23a = ffma2(va.y, wpa, t23a);
                ull wpb = pk1(wm1r[c + 1]);
                ulonglong2 vb = bvG[c + 1];
                t01b = ffma2(vb.x, wpb, t01b);
                t23b = ffma2(vb.y, wpb, t23b);
            }
            ull t01 = fadd2(t01a, t01b), t23 = fadd2(t23a, t23b);
            float t0, t1, t2, t3;
            upk(t01, t0, t1); upk(t23, t2, t3);
            *mbT = make_float4(fmaxf(t0, 0.f), fmaxf(t1, 0.f),
                               fmaxf(t2, 0.f), fmaxf(t3, 0.f));
            __syncwarp();

            // stage gm2: u = t2b + Wm2 @ r (4 chains); relu+max folded
            ull u01a = pk1(biasT), u23a = u01a;
            ull u01b = 0ULL, u23b = 0ULL;
            #pragma unroll
            for (int c = 0; c < 32; c += 2) {
                ull wpa = pk1(wm2r[c]);
                ulonglong2 va = bvT[c];
                u01a = ffma2(va.x, wpa, u01a);
                u23a = ffma2(va.y, wpa, u23a);
                ull wpb = pk1(wm2r[c + 1]);
                ulonglong2 vb = bvT[c + 1];
                u01b = ffma2(vb.x, wpb, u01b);
                u23b = ffma2(vb.y, wpb, u23b);
            }
            ull u01 = fadd2(u01a, u01b), u23 = fadd2(u23a, u23b);
            float u0, u1, u2, u3;
            upk(u01, u0, u1); upk(u23, u2, u3);
            um = fmaxf(um, fmaxf(fmaxf(u0, u1), fmaxf(u2, u3)));
        }

        g_gpool[((size_t)b * 32 + o) * NM + mt * 32 + ml] = um;
    }
}

// ---------------------------------------------------------------------------
// Kernel 2: cosine sim + argmax gather + MLP + final layers -> out
// grid 512 = B*4 m-tiles of 32; block 256 (unchanged, ~59us measured)
// ---------------------------------------------------------------------------
__global__ __launch_bounds__(256) void k_out(
    const float* __restrict__ x_label, const float* __restrict__ x_object,
    const float* __restrict__ template_xyz,
    const float* __restrict__ mlp_w1, const float* __restrict__ mlp_s1,
    const float* __restrict__ mlp_t1, const float* __restrict__ mlp_w2,
    const float* __restrict__ mlp_s2, const float* __restrict__ mlp_t2,
    const float* __restrict__ fl_w1, const float* __restrict__ fl_s1,
    const float* __restrict__ fl_t1, const float* __restrict__ fl_w2,
    const float* __restrict__ fl_b2, float* __restrict__ out)
{
    __shared__ float xo_s[32][64];
    __shared__ float w1T[68][32];
    __shared__ float w2T[32][32];
    __shared__ float na_s[64];
    __shared__ float hs[32][33];
    __shared__ float fu[64][33];
    __shared__ float o1s[64][33];
    __shared__ float sb[8][32];
    __shared__ int   si[8][32];

    const int b = blockIdx.x >> 2, mt = blockIdx.x & 3;
    const int tid = threadIdx.x, ml = tid & 31, p = tid >> 5;
    const int m = mt * 32 + ml;

    for (int i = tid; i < 2048; i += 256)
        ((float*)xo_s)[i] = x_object[(size_t)b * 2048 + i];
    for (int i = tid; i < 68 * 32; i += 256) {
        int j = i >> 5, o = i & 31;
        w1T[j][o] = mlp_w1[o * 68 + j];
    }
    for (int i = tid; i < 1024; i += 256) {
        int c = i >> 5, o = i & 31;
        w2T[c][o] = mlp_w2[o * 32 + c];
    }
    for (int i = tid; i < 1024; i += 256) {
        int c = i >> 5, q = i & 31;
        fu[32 + c][q] = g_gpool[((size_t)b * 32 + c) * NM + mt * 32 + q];
    }
    __syncthreads();
    if (tid < 64) {
        float s = 0.f;
        #pragma unroll
        for (int c = 0; c < 32; c++) { float v = xo_s[c][tid]; s += v * v; }
        na_s[tid] = sqrtf(s);
    }

    float xl[32];
    #pragma unroll
    for (int c = 0; c < 32; c++)
        xl[c] = x_label[(size_t)b * 4096 + c * 128 + m];
    float nb = 0.f;
    #pragma unroll
    for (int c = 0; c < 32; c++) nb += xl[c] * xl[c];
    nb = sqrtf(nb);
    __syncthreads();

    float best = -3.4e38f; int bidx = 8 * p;
    #pragma unroll 1
    for (int n = 8 * p; n < 8 * p + 8; n++) {
        float num = 0.f;
        #pragma unroll
        for (int c = 0; c < 32; c++) num += xo_s[c][n] * xl[c];
        float cs = num / fmaxf(na_s[n] * nb, 1e-8f);
        if (cs > best) { best = cs; bidx = n; }
    }
    sb[p][ml] = best; si[p][ml] = bidx;
    __syncthreads();
    best = sb[0][ml]; bidx = si[0][ml];
    #pragma unroll
    for (int pp = 1; pp < 8; pp++)
        if (sb[pp][ml] > best) { best = sb[pp][ml]; bidx = si[pp][ml]; }

    float hr[4];
    {
        const float* tx = template_xyz + (size_t)b * 192 + bidx * 3;
        float a0 = tx[0], a1 = tx[1], a2 = tx[2];
        #pragma unroll
        for (int oo = 0; oo < 4; oo++) {
            int o = 4 * p + oo;
            hr[oo] = w1T[0][o] * best + w1T[1][o] * a0 +
                     w1T[2][o] * a1 + w1T[3][o] * a2;
        }
    }
    #pragma unroll
    for (int c = 0; c < 32; c++) {
        float xoc = xo_s[c][bidx];
        #pragma unroll
        for (int oo = 0; oo < 4; oo++) hr[oo] += w1T[4 + c][4 * p + oo] * xoc;
    }
    #pragma unroll
    for (int c = 0; c < 32; c++) {
        float v = xl[c];
        #pragma unroll
        for (int oo = 0; oo < 4; oo++) hr[oo] += w1T[36 + c][4 * p + oo] * v;
    }
    #pragma unroll
    for (int oo = 0; oo < 4; oo++) {
        int o = 4 * p + oo;
        hs[ml][o] = fmaxf(mlp_s1[o] * hr[oo] + mlp_t1[o], 0.f);
    }
    __syncthreads();

    float h2r[4] = {0.f, 0.f, 0.f, 0.f};
    #pragma unroll
    for (int c = 0; c < 32; c++) {
        float v = hs[ml][c];
        #pragma unroll
        for (int oo = 0; oo < 4; oo++) h2r[oo] += w2T[c][4 * p + oo] * v;
    }
    #pragma unroll
    for (int oo = 0; oo < 4; oo++) {
        int o = 4 * p + oo;
        fu[o][ml] = fmaxf(mlp_s2[o] * h2r[oo] + mlp_t2[o], 0.f);
    }
    __syncthreads();

    float fv[64];
    #pragma unroll
    for (int c = 0; c < 64; c++) fv[c] = fu[c][ml];
    #pragma unroll 2
    for (int oo = 0; oo < 8; oo++) {
        int o = 8 * p + oo;
        float acc = 0.f;
        const float4* wp4 = (const float4*)(fl_w1 + o * 64);
        #pragma unroll
        for (int c4 = 0; c4 < 16; c4++) {
            float4 ww = __ldg(&wp4[c4]);
            acc += ww.x * fv[4 * c4] + ww.y * fv[4 * c4 + 1] +
                   ww.z * fv[4 * c4 + 2] + ww.w * fv[4 * c4 + 3];
        }
        o1s[o][ml] = fmaxf(fl_s1[o] * acc + fl_t1[o], 0.f);
    }
    __syncthreads();

    float ov[64];
    #pragma unroll
    for (int c = 0; c < 64; c++) ov[c] = o1s[c][ml];
    #pragma unroll 2
    for (int oo = 0; oo < 8; oo++) {
        int o = 8 * p + oo;
        float acc = fl_b2[o];
        const float4* wp4 = (const float4*)(fl_w2 + o * 64);
        #pragma unroll
        for (int c4 = 0; c4 < 16; c4++) {
            float4 ww = __ldg(&wp4[c4]);
            acc += ww.x * ov[4 * c4] + ww.y * ov[4 * c4 + 1] +
                   ww.z * ov[4 * c4 + 2] + ww.w * ov[4 * c4 + 3];
        }
        out[((size_t)b * 64 + o) * NM + m] = acc;
    }
}

extern "C" void kernel_launch(void* const* d_in, const int* in_sizes, int n_in,
                              void* d_out, int out_size)
{
    const float* x_label      = (const float*)d_in[0];
    const float* x_object     = (const float*)d_in[1];
    const float* template_xyz = (const float*)d_in[2];
    const float* mlp_w1 = (const float*)d_in[3];
    const float* mlp_s1 = (const float*)d_in[4];
    const float* mlp_t1 = (const float*)d_in[5];
    const float* mlp_w2 = (const float*)d_in[6];
    const float* mlp_s2 = (const float*)d_in[7];
    const float* mlp_t2 = (const float*)d_in[8];
    const float* gw_w1  = (const float*)d_in[9];
    const float* gw_b1  = (const float*)d_in[10];
    const float* gw_s   = (const float*)d_in[11];
    const float* gw_t   = (const float*)d_in[12];
    const float* gw_w2  = (const float*)d_in[13];
    const float* gw_b2  = (const float*)d_in[14];
    const float* gm_w1  = (const float*)d_in[15];
    const float* gm_s1  = (const float*)d_in[16];
    const float* gm_t1  = (const float*)d_in[17];
    const float* gm_w2  = (const float*)d_in[18];
    const float* gm_s2  = (const float*)d_in[19];
    const float* gm_t2  = (const float*)d_in[20];
    const float* fl_w1  = (const float*)d_in[21];
    const float* fl_s1  = (const float*)d_in[22];
    const float* fl_t1  = (const float*)d_in[23];
    const float* fl_w2  = (const float*)d_in[24];
    const float* fl_b2  = (const float*)d_in[25];

    k_gpool<<<512, 128>>>(x_label, x_object, template_xyz,
                          gw_w1, gw_b1, gw_s, gw_t, gw_w2, gw_b2,
                          gm_w1, gm_s1, gm_t1, gm_w2, gm_s2, gm_t2);
    k_out<<<512, 256>>>(x_label, x_object, template_xyz,
                        mlp_w1, mlp_s1, mlp_t1, mlp_w2, mlp_s2, mlp_t2,
                        fl_w1, fl_s1, fl_t1, fl_w2, fl_b2, (float*)d_out);
}

// round 12
// speedup vs baseline: 1.0159x; 1.0159x over previous
#include <cuda_runtime.h>

#define BB 128
#define NM 128

typedef unsigned long long ull;

__device__ __forceinline__ ull pk(float lo, float hi) {
    ull r; asm("mov.b64 %0,{%1,%2};" : "=l"(r) : "f"(lo), "f"(hi)); return r;
}
__device__ __forceinline__ ull pk1(float v) {
    ull r; asm("mov.b64 %0,{%1,%1};" : "=l"(r) : "f"(v)); return r;
}
__device__ __forceinline__ void upk(ull v, float& lo, float& hi) {
    asm("mov.b64 {%0,%1},%2;" : "=f"(lo), "=f"(hi) : "l"(v));
}
__device__ __forceinline__ ull ffma2(ull a, ull b, ull c) {
    ull d; asm("fma.rn.f32x2 %0,%1,%2,%3;" : "=l"(d) : "l"(a), "l"(b), "l"(c)); return d;
}

// ---------------------------------------------------------------------------
// Fully fused kernel: gpool (R10 main loop) + cos/argmax/MLP/final layers.
// grid 512 = B*4 m-tiles of 32; block 128 = 4 warps.
// One 48,256-byte smem arena, phase-disjoint aliasing:
//   gpool phase:  xoT[0..2112) Bn[2112..4224) Tn[4224..6336) As[6336..7392)
//                 Wst[7392..10464) {bufT=[7392..7904), gps=[7904..8960)}
//                 xls/bufG[10464..11488) bufL[11488..12000) b2s/ct2s[12000..12064)
//   k_out phase (after sync; gpool arrays dead except xoT + gps):
//                 o1s[2112..4224) w2T[4288..5312) na_s[5312..5376)
//                 sb[5376..5504) si[5504..5632) hs[6336..7392) fuh2[8960..10016)
//                 w1T[2112..4288)  (w1T dies before o1s is written)
// ---------------------------------------------------------------------------
__global__ __launch_bounds__(128) void k_fused(
    const float* __restrict__ x_label, const float* __restrict__ x_object,
    const float* __restrict__ template_xyz,
    const float* __restrict__ mlp_w1, const float* __restrict__ mlp_s1,
    const float* __restrict__ mlp_t1, const float* __restrict__ mlp_w2,
    const float* __restrict__ mlp_s2, const float* __restrict__ mlp_t2,
    const float* __restrict__ gw_w1, const float* __restrict__ gw_b1,
    const float* __restrict__ gw_s,  const float* __restrict__ gw_t,
    const float* __restrict__ gw_w2, const float* __restrict__ gw_b2,
    const float* __restrict__ gm_w1, const float* __restrict__ gm_s1,
    const float* __restrict__ gm_t1, const float* __restrict__ gm_w2,
    const float* __restrict__ gm_s2, const float* __restrict__ gm_t2,
    const float* __restrict__ fl_w1, const float* __restrict__ fl_s1,
    const float* __restrict__ fl_t1, const float* __restrict__ fl_w2,
    const float* __restrict__ fl_b2, float* __restrict__ out)
{
    __shared__ __align__(16) float S[12064];   // 48256 bytes

    float* xoT  = S;            // [64][33]
    float* Bn   = S + 2112;     // [64][33]
    float* Tn   = S + 4224;     // [64][33]
    float* As   = S + 6336;     // [32][33]
    float* Wst  = S + 7392;     // [3][32][32] staging
    float* gps  = S + 7904;     // [32][33] gpool tile (inside dead Wst, after bufT)
    float* xls  = S + 10464;    // [32][32]; bufG alias
    float* bufL = S + 11488;    // [4][32][4]
    float* b2s  = S + 12000;    // [32]
    float* ct2s = S + 12032;    // [32]

    const int tid = threadIdx.x;
    const int b = blockIdx.x >> 2, mt = blockIdx.x & 3;

    // ============== PHASE A: staging ==============
    for (int i = tid; i < 2048; i += 128) {
        int c = i >> 6, n = i & 63;
        xoT[n * 33 + c] = x_object[(size_t)b * 2048 + i];
    }
    for (int i = tid; i < 1024; i += 128) {
        int c = i >> 5, ml = i & 31;
        xls[c * 32 + ml] = x_label[(size_t)b * 4096 + c * 128 + mt * 32 + ml];
    }
    for (int i = tid; i < 1024; i += 128) {
        int c = i >> 5, o = i & 31;
        Wst[c * 32 + o]        = gw_w2[o * 32 + c];
        Wst[1024 + c * 32 + o] = gm_s1[o] * gm_w1[o * 35 + 3 + c];
        Wst[2048 + c * 32 + o] = gm_s2[o] * gm_w2[o * 32 + c];
    }
    if (tid < 32) { b2s[tid] = gw_b2[tid]; ct2s[tid] = gm_t2[tid]; }
    __syncthreads();

    // ============== PHASE B: precompute ==============
    for (int i = tid; i < 2048; i += 128) {
        int o = i >> 6, n = i & 63;
        float a = 0.f;
        #pragma unroll
        for (int c = 0; c < 32; c++) a += gw_w1[o * 32 + c] * xoT[n * 33 + c];
        Bn[n * 33 + o] = -gw_s[o] * a;
        const float* tx = template_xyz + (size_t)b * 192 + n * 3;
        Tn[n * 33 + o] = gm_s1[o] * (gm_w1[o * 35] * tx[0] + gm_w1[o * 35 + 1] * tx[1] +
                                     gm_w1[o * 35 + 2] * tx[2]) + gm_t1[o];
    }
    for (int i = tid; i < 1024; i += 128) {
        int o = i >> 5, ml = i & 31;
        float a = 0.f;
        #pragma unroll
        for (int c = 0; c < 32; c++) a += gw_w1[o * 32 + c] * xls[c * 32 + ml];
        As[ml * 33 + o] = gw_s[o] * a + gw_s[o] * gw_b1[o] + gw_t[o];
    }
    __syncthreads();

    // ---- hoist weight columns into registers ----
    const int w = tid >> 5, o = tid & 31;
    float w2r[32], wm1r[32], wm2r[32];
    #pragma unroll
    for (int c = 0; c < 32; c++) {
        w2r[c]  = Wst[c * 32 + o];
        wm1r[c] = Wst[1024 + c * 32 + o];
        wm2r[c] = Wst[2048 + c * 32 + o];
    }
    const float bias2 = b2s[o], biasT = ct2s[o];
    __syncthreads();   // staging becomes exchange buffers / gps

    float4* mbL = (float4*)(bufL + (w * 32 + o) * 4);
    float4* mbG = (float4*)(xls  + (w * 32 + o) * 4);
    float4* mbT = (float4*)(Wst  + (w * 32 + o) * 4);
    const ulonglong2* bvL = (const ulonglong2*)(bufL + w * 128);
    const ulonglong2* bvG = (const ulonglong2*)(xls  + w * 128);
    const ulonglong2* bvT = (const ulonglong2*)(Wst  + w * 128);

    // ============== PHASE C: gpool main loop (R10 form) ==============
    #pragma unroll 1
    for (int mi = 0; mi < 8; mi++) {
        const int ml = w * 8 + mi;
        const float as = As[ml * 33 + o];
        float um = 0.f;

        #pragma unroll 1
        for (int j = 0; j < 16; j++) {
            const int n0 = 4 * j;

            float z0 = as + Bn[(n0 + 0) * 33 + o];
            float z1 = as + Bn[(n0 + 1) * 33 + o];
            float z2 = as + Bn[(n0 + 2) * 33 + o];
            float z3 = as + Bn[(n0 + 3) * 33 + o];
            *mbL = make_float4(fmaxf(z0, 0.2f * z0), fmaxf(z1, 0.2f * z1),
                               fmaxf(z2, 0.2f * z2), fmaxf(z3, 0.2f * z3));
            __syncwarp();

            ull q01 = pk1(bias2), q23 = q01;
            #pragma unroll
            for (int c = 0; c < 32; c++) {
                ull wp = pk1(w2r[c]);
                ulonglong2 v = bvL[c];
                q01 = ffma2(v.x, wp, q01);
                q23 = ffma2(v.y, wp, q23);
            }

            float q0, q1, q2, q3;
            upk(q01, q0, q1); upk(q23, q2, q3);
            float g0 = __fdividef(xoT[(n0 + 0) * 33 + o], 1.f + __expf(-q0));
            float g1 = __fdividef(xoT[(n0 + 1) * 33 + o], 1.f + __expf(-q1));
            float g2 = __fdividef(xoT[(n0 + 2) * 33 + o], 1.f + __expf(-q2));
            float g3 = __fdividef(xoT[(n0 + 3) * 33 + o], 1.f + __expf(-q3));
            *mbG = make_float4(g0, g1, g2, g3);
            __syncwarp();

            ull t01 = pk(Tn[(n0 + 0) * 33 + o], Tn[(n0 + 1) * 33 + o]);
            ull t23 = pk(Tn[(n0 + 2) * 33 + o], Tn[(n0 + 3) * 33 + o]);
            #pragma unroll
            for (int c = 0; c < 32; c++) {
                ull wp = pk1(wm1r[c]);
                ulonglong2 v = bvG[c];
                t01 = ffma2(v.x, wp, t01);
                t23 = ffma2(v.y, wp, t23);
            }
            float t0, t1, t2, t3;
            upk(t01, t0, t1); upk(t23, t2, t3);
            *mbT = make_float4(fmaxf(t0, 0.f), fmaxf(t1, 0.f),
                               fmaxf(t2, 0.f), fmaxf(t3, 0.f));
            __syncwarp();

            ull u01 = pk1(biasT), u23 = u01;
            #pragma unroll
            for (int c = 0; c < 32; c++) {
                ull wp = pk1(wm2r[c]);
                ulonglong2 v = bvT[c];
                u01 = ffma2(v.x, wp, u01);
                u23 = ffma2(v.y, wp, u23);
            }
            float u0, u1, u2, u3;
            upk(u01, u0, u1); upk(u23, u2, u3);
            um = fmaxf(um, fmaxf(fmaxf(u0, u1), fmaxf(u2, u3)));
        }

        gps[o * 33 + ml] = um;   // gpool tile to smem (not global)
    }
    __syncthreads();

    // ============== PHASE D: k_out staging ==============
    float* w1T  = S + 2112;     // [68][32] over dead Bn(+Tn head)
    float* w2T  = S + 4288;     // [32][32]
    float* na_s = S + 5312;     // [64]
    float* sb   = S + 5376;     // [4][32]
    int*   si   = (int*)(S + 5504);  // [4][32]
    float* hs   = S + 6336;     // [32][33] over dead As
    float* fuh2 = S + 8960;     // [32][33] over dead Wst tail
    float* o1s  = S + 2112;     // [64][33] over dead w1T (dies before fl1)

    for (int i = tid; i < 2176; i += 128) {
        int j = i >> 5, oo = i & 31;
        w1T[j * 32 + oo] = mlp_w1[oo * 68 + j];
    }
    for (int i = tid; i < 1024; i += 128) {
        int c = i >> 5, oo = i & 31;
        w2T[c * 32 + oo] = mlp_w2[oo * 32 + c];
    }
    if (tid < 64) {
        float s = 0.f;
        #pragma unroll
        for (int c = 0; c < 32; c++) { float v = xoT[tid * 33 + c]; s += v * v; }
        na_s[tid] = sqrtf(s);
    }

    const int ml = tid & 31, p = tid >> 5;
    const int m = mt * 32 + ml;

    float xl[32];
    #pragma unroll
    for (int c = 0; c < 32; c++)
        xl[c] = x_label[(size_t)b * 4096 + c * 128 + m];
    float nb = 0.f;
    #pragma unroll
    for (int c = 0; c < 32; c++) nb += xl[c] * xl[c];
    nb = sqrtf(nb);
    __syncthreads();

    // ============== PHASE E: argmax (n split across 4 parts) ==============
    float best = -3.4e38f; int bidx = 16 * p;
    #pragma unroll 1
    for (int n = 16 * p; n < 16 * p + 16; n++) {
        float num = 0.f;
        #pragma unroll
        for (int c = 0; c < 32; c++) num += xoT[n * 33 + c] * xl[c];
        float cs = num / fmaxf(na_s[n] * nb, 1e-8f);
        if (cs > best) { best = cs; bidx = n; }
    }
    sb[p * 32 + ml] = best; si[p * 32 + ml] = bidx;
    __syncthreads();
    best = sb[ml]; bidx = si[ml];
    #pragma unroll
    for (int pp = 1; pp < 4; pp++) {
        if (sb[pp * 32 + ml] > best) { best = sb[pp * 32 + ml]; bidx = si[pp * 32 + ml]; }
    }

    // ============== PHASE F: MLP layer 1 (o in [8p,8p+8)) ==============
    float hr[8];
    {
        const float* tx = template_xyz + (size_t)b * 192 + bidx * 3;
        float a0 = tx[0], a1 = tx[1], a2 = tx[2];
        #pragma unroll
        for (int oo = 0; oo < 8; oo++) {
            int oc = 8 * p + oo;
            hr[oo] = w1T[0 * 32 + oc] * best + w1T[1 * 32 + oc] * a0 +
                     w1T[2 * 32 + oc] * a1 + w1T[3 * 32 + oc] * a2;
        }
    }
    #pragma unroll
    for (int c = 0; c < 32; c++) {
        float xoc = xoT[bidx * 33 + c];
        #pragma unroll
        for (int oo = 0; oo < 8; oo++) hr[oo] += w1T[(4 + c) * 32 + 8 * p + oo] * xoc;
    }
    #pragma unroll
    for (int c = 0; c < 32; c++) {
        float v = xl[c];
        #pragma unroll
        for (int oo = 0; oo < 8; oo++) hr[oo] += w1T[(36 + c) * 32 + 8 * p + oo] * v;
    }
    #pragma unroll
    for (int oo = 0; oo < 8; oo++) {
        int oc = 8 * p + oo;
        hs[ml * 33 + oc] = fmaxf(mlp_s1[oc] * hr[oo] + mlp_t1[oc], 0.f);
    }
    __syncthreads();

    // ============== PHASE G: MLP layer 2 -> fuh2 ==============
    float h2r[8] = {0.f, 0.f, 0.f, 0.f, 0.f, 0.f, 0.f, 0.f};
    #pragma unroll
    for (int c = 0; c < 32; c++) {
        float v = hs[ml * 33 + c];
        #pragma unroll
        for (int oo = 0; oo < 8; oo++) h2r[oo] += w2T[c * 32 + 8 * p + oo] * v;
    }
    #pragma unroll
    for (int oo = 0; oo < 8; oo++) {
        int oc = 8 * p + oo;
        fuh2[oc * 33 + ml] = fmaxf(mlp_s2[oc] * h2r[oo] + mlp_t2[oc], 0.f);
    }
    __syncthreads();

    // ============== PHASE H: fl1 (o in [16p,16p+16)) ==============
    float fv[64];
    #pragma unroll
    for (int c = 0; c < 32; c++) fv[c] = fuh2[c * 33 + ml];
    #pragma unroll
    for (int c = 0; c < 32; c++) fv[32 + c] = gps[c * 33 + ml];
    #pragma unroll 4
    for (int oo = 0; oo < 16; oo++) {
        int oc = 16 * p + oo;
        float acc = 0.f;
        const float4* wp4 = (const float4*)(fl_w1 + oc * 64);
        #pragma unroll
        for (int c4 = 0; c4 < 16; c4++) {
            float4 ww = __ldg(&wp4[c4]);
            acc += ww.x * fv[4 * c4] + ww.y * fv[4 * c4 + 1] +
                   ww.z * fv[4 * c4 + 2] + ww.w * fv[4 * c4 + 3];
        }
        o1s[oc * 33 + ml] = fmaxf(fl_s1[oc] * acc + fl_t1[oc], 0.f);
    }
    __syncthreads();

    // ============== PHASE I: fl2 ==============
    float ov[64];
    #pragma unroll
    for (int c = 0; c < 64; c++) ov[c] = o1s[c * 33 + ml];
    #pragma unroll 4
    for (int oo = 0; oo < 16; oo++) {
        int oc = 16 * p + oo;
        float acc = fl_b2[oc];
        const float4* wp4 = (const float4*)(fl_w2 + oc * 64);
        #pragma unroll
        for (int c4 = 0; c4 < 16; c4++) {
            float4 ww = __ldg(&wp4[c4]);
            acc += ww.x * ov[4 * c4] + ww.y * ov[4 * c4 + 1] +
                   ww.z * ov[4 * c4 + 2] + ww.w * ov[4 * c4 + 3];
        }
        out[((size_t)b * 64 + oc) * NM + m] = acc;
    }
}

extern "C" void kernel_launch(void* const* d_in, const int* in_sizes, int n_in,
                              void* d_out, int out_size)
{
    const float* x_label      = (const float*)d_in[0];
    const float* x_object     = (const float*)d_in[1];
    const float* template_xyz = (const float*)d_in[2];
    const float* mlp_w1 = (const float*)d_in[3];
    const float* mlp_s1 = (const float*)d_in[4];
    const float* mlp_t1 = (const float*)d_in[5];
    const float* mlp_w2 = (const float*)d_in[6];
    const float* mlp_s2 = (const float*)d_in[7];
    const float* mlp_t2 = (const float*)d_in[8];
    const float* gw_w1  = (const float*)d_in[9];
    const float* gw_b1  = (const float*)d_in[10];
    const float* gw_s   = (const float*)d_in[11];
    const float* gw_t   = (const float*)d_in[12];
    const float* gw_w2  = (const float*)d_in[13];
    const float* gw_b2  = (const float*)d_in[14];
    const float* gm_w1  = (const float*)d_in[15];
    const float* gm_s1  = (const float*)d_in[16];
    const float* gm_t1  = (const float*)d_in[17];
    const float* gm_w2  = (const float*)d_in[18];
    const float* gm_s2  = (const float*)d_in[19];
    const float* gm_t2  = (const float*)d_in[20];
    const float* fl_w1  = (const float*)d_in[21];
    const float* fl_s1  = (const float*)d_in[22];
    const float* fl_t1  = (const float*)d_in[23];
    const float* fl_w2  = (const float*)d_in[24];
    const float* fl_b2  = (const float*)d_in[25];

    k_fused<<<512, 128>>>(x_label, x_object, template_xyz,
                          mlp_w1, mlp_s1, mlp_t1, mlp_w2, mlp_s2, mlp_t2,
                          gw_w1, gw_b1, gw_s, gw_t, gw_w2, gw_b2,
                          gm_w1, gm_s1, gm_t1, gm_w2, gm_s2, gm_t2,
                          fl_w1, fl_s1, fl_t1, fl_w2, fl_b2, (float*)d_out);
}

// round 13
// speedup vs baseline: 1.7410x; 1.7137x over previous
#include <cuda_runtime.h>

#define BB 128
#define NM 128

__device__ float g_gpool[BB * 32 * NM];

__device__ __forceinline__ unsigned f2tf(float x) {
    unsigned u; asm("cvt.rna.tf32.f32 %0, %1;" : "=r"(u) : "f"(x)); return u;
}
__device__ __forceinline__ void mma8(float& d0, float& d1, float& d2, float& d3,
                                     unsigned a0, unsigned a1, unsigned a2, unsigned a3,
                                     unsigned b0, unsigned b1) {
    asm("mma.sync.aligned.m16n8k8.row.col.f32.tf32.tf32.f32 "
        "{%0,%1,%2,%3},{%4,%5,%6,%7},{%8,%9},{%0,%1,%2,%3};"
        : "+f"(d0), "+f"(d1), "+f"(d2), "+f"(d3)
        : "r"(a0), "r"(a1), "r"(a2), "r"(a3), "r"(b0), "r"(b1));
}

// ---------------------------------------------------------------------------
// Kernel 1: global-attention branch -> g_gpool via tf32 tensor-core MMA.
// grid 512 = B*4 m-tiles of 32; block 128 = 4 warps; warp w owns ml in
// [8w,8w+8). Per (m, r) warp-tile: 16 n-rows x 32 ch cascade, 3 stages of
// m16n8k8 tf32 MMA (activations split hi/lo -> fp32-grade except tf32
// rounding of weights). Weights = 96 register B-fragments.
// ---------------------------------------------------------------------------
__global__ __launch_bounds__(128) void k_gpool(
    const float* __restrict__ x_label, const float* __restrict__ x_object,
    const float* __restrict__ template_xyz,
    const float* __restrict__ gw_w1, const float* __restrict__ gw_b1,
    const float* __restrict__ gw_s,  const float* __restrict__ gw_t,
    const float* __restrict__ gw_w2, const float* __restrict__ gw_b2,
    const float* __restrict__ gm_w1, const float* __restrict__ gm_s1,
    const float* __restrict__ gm_t1, const float* __restrict__ gm_w2,
    const float* __restrict__ gm_s2, const float* __restrict__ gm_t2)
{
    __shared__ float xoT[64 * 36];   // [n][c], stride 36
    __shared__ float Bn[64 * 36];    // [n][c] = -s*(W1@xo)
    __shared__ float Tn[64 * 36];    // [n][o] gm1 xyz part + t1
    __shared__ float As[32 * 36];    // [ml][c] = s*(W1@xl + b1) + t
    __shared__ float xls[32 * 32];

    const int tid = threadIdx.x;
    const int b = blockIdx.x >> 2, mt = blockIdx.x & 3;

    // ---- stage inputs ----
    for (int i = tid; i < 2048; i += 128) {
        int c = i >> 6, n = i & 63;
        xoT[n * 36 + c] = x_object[(size_t)b * 2048 + i];
    }
    for (int i = tid; i < 1024; i += 128) {
        int c = i >> 5, ml = i & 31;
        xls[c * 32 + ml] = x_label[(size_t)b * 4096 + c * 128 + mt * 32 + ml];
    }
    __syncthreads();

    // ---- per-(b,n) and per-(b,m) precompute ----
    for (int i = tid; i < 2048; i += 128) {
        int o = i >> 6, n = i & 63;
        float a = 0.f;
        #pragma unroll
        for (int c = 0; c < 32; c++) a += gw_w1[o * 32 + c] * xoT[n * 36 + c];
        Bn[n * 36 + o] = -gw_s[o] * a;
        const float* tx = template_xyz + (size_t)b * 192 + n * 3;
        Tn[n * 36 + o] = gm_s1[o] * (gm_w1[o * 35] * tx[0] + gm_w1[o * 35 + 1] * tx[1] +
                                     gm_w1[o * 35 + 2] * tx[2]) + gm_t1[o];
    }
    for (int i = tid; i < 1024; i += 128) {
        int o = i >> 5, ml = i & 31;
        float a = 0.f;
        #pragma unroll
        for (int c = 0; c < 32; c++) a += gw_w1[o * 32 + c] * xls[c * 32 + ml];
        As[ml * 36 + o] = gw_s[o] * a + gw_s[o] * gw_b1[o] + gw_t[o];
    }

    // ---- per-lane weight fragments (tf32, B col-major layout) ----
    const int w = tid >> 5, lane = tid & 31;
    const int g = lane >> 2, t = lane & 3;

    unsigned w0[4][4][2], w1f[4][4][2], w2f[4][4][2];
    float b2a[4], b2b[4], ct2a[4], ct2b[4];
    #pragma unroll
    for (int nt = 0; nt < 4; nt++) {
        int no = 8 * nt + g;
        float s1v = gm_s1[no], s2v = gm_s2[no];
        #pragma unroll
        for (int kt = 0; kt < 4; kt++) {
            int k0 = 8 * kt + t;
            w0[kt][nt][0]  = f2tf(gw_w2[no * 32 + k0]);
            w0[kt][nt][1]  = f2tf(gw_w2[no * 32 + k0 + 4]);
            w1f[kt][nt][0] = f2tf(s1v * gm_w1[no * 35 + 3 + k0]);
            w1f[kt][nt][1] = f2tf(s1v * gm_w1[no * 35 + 3 + k0 + 4]);
            w2f[kt][nt][0] = f2tf(s2v * gm_w2[no * 32 + k0]);
            w2f[kt][nt][1] = f2tf(s2v * gm_w2[no * 32 + k0 + 4]);
        }
        b2a[nt]  = gw_b2[8 * nt + 2 * t];
        b2b[nt]  = gw_b2[8 * nt + 2 * t + 1];
        ct2a[nt] = gm_t2[8 * nt + 2 * t];
        ct2b[nt] = gm_t2[8 * nt + 2 * t + 1];
    }
    __syncthreads();

    const int s1l = (lane & ~3) | (t >> 1);
    const int s2l = s1l + 2;
    const bool odd = (t & 1) != 0;

    #pragma unroll 1
    for (int mi = 0; mi < 8; mi++) {
        const int ml = w * 8 + mi;
        float asv[8];
        #pragma unroll
        for (int kt = 0; kt < 4; kt++) {
            asv[2 * kt]     = As[ml * 36 + 8 * kt + t];
            asv[2 * kt + 1] = As[ml * 36 + 8 * kt + t + 4];
        }
        float mm[4][2];
        #pragma unroll
        for (int nt = 0; nt < 4; nt++) { mm[nt][0] = 0.f; mm[nt][1] = 0.f; }

        #pragma unroll 1
        for (int r = 0; r < 4; r++) {
            const int r0 = 16 * r + g, r1 = r0 + 8;

            // ---- stage 1: build A fragments of L = leaky(as + Bn) ----
            unsigned ah[4][4], al[4][4];
            #pragma unroll
            for (int kt = 0; kt < 4; kt++) {
                int c0 = 8 * kt + t, c1 = c0 + 4;
                float x00 = asv[2 * kt]     + Bn[r0 * 36 + c0];
                float x10 = asv[2 * kt]     + Bn[r1 * 36 + c0];
                float x01 = asv[2 * kt + 1] + Bn[r0 * 36 + c1];
                float x11 = asv[2 * kt + 1] + Bn[r1 * 36 + c1];
                x00 = fmaxf(x00, 0.2f * x00); x10 = fmaxf(x10, 0.2f * x10);
                x01 = fmaxf(x01, 0.2f * x01); x11 = fmaxf(x11, 0.2f * x11);
                ah[kt][0] = f2tf(x00); al[kt][0] = f2tf(x00 - __uint_as_float(ah[kt][0]));
                ah[kt][1] = f2tf(x10); al[kt][1] = f2tf(x10 - __uint_as_float(ah[kt][1]));
                ah[kt][2] = f2tf(x01); al[kt][2] = f2tf(x01 - __uint_as_float(ah[kt][2]));
                ah[kt][3] = f2tf(x11); al[kt][3] = f2tf(x11 - __uint_as_float(ah[kt][3]));
            }

            // ---- stage gw2 + sigmoid gate ----
            float dd[4][4];
            #pragma unroll
            for (int nt = 0; nt < 4; nt++) {
                float d0 = b2a[nt], d1 = b2b[nt], d2 = b2a[nt], d3 = b2b[nt];
                #pragma unroll
                for (int kt = 0; kt < 4; kt++) {
                    mma8(d0, d1, d2, d3, ah[kt][0], ah[kt][1], ah[kt][2], ah[kt][3],
                         w0[kt][nt][0], w0[kt][nt][1]);
                    mma8(d0, d1, d2, d3, al[kt][0], al[kt][1], al[kt][2], al[kt][3],
                         w0[kt][nt][0], w0[kt][nt][1]);
                }
                int o0 = 8 * nt + 2 * t;
                dd[nt][0] = __fdividef(xoT[r0 * 36 + o0],     1.f + __expf(-d0));
                dd[nt][1] = __fdividef(xoT[r0 * 36 + o0 + 1], 1.f + __expf(-d1));
                dd[nt][2] = __fdividef(xoT[r1 * 36 + o0],     1.f + __expf(-d2));
                dd[nt][3] = __fdividef(xoT[r1 * 36 + o0 + 1], 1.f + __expf(-d3));
            }

            // ---- D->A transform ----
            #pragma unroll
            for (int j = 0; j < 4; j++) {
                float e0 = __shfl_sync(0xffffffffu, dd[j][0], s1l);
                float e1 = __shfl_sync(0xffffffffu, dd[j][1], s1l);
                float f0 = __shfl_sync(0xffffffffu, dd[j][0], s2l);
                float f1 = __shfl_sync(0xffffffffu, dd[j][1], s2l);
                float g0 = __shfl_sync(0xffffffffu, dd[j][2], s1l);
                float g1 = __shfl_sync(0xffffffffu, dd[j][3], s1l);
                float h0 = __shfl_sync(0xffffffffu, dd[j][2], s2l);
                float h1 = __shfl_sync(0xffffffffu, dd[j][3], s2l);
                float ra0 = odd ? e1 : e0;
                float ra2 = odd ? f1 : f0;
                float ra1 = odd ? g1 : g0;
                float ra3 = odd ? h1 : h0;
                ah[j][0] = f2tf(ra0); al[j][0] = f2tf(ra0 - __uint_as_float(ah[j][0]));
                ah[j][1] = f2tf(ra1); al[j][1] = f2tf(ra1 - __uint_as_float(ah[j][1]));
                ah[j][2] = f2tf(ra2); al[j][2] = f2tf(ra2 - __uint_as_float(ah[j][2]));
                ah[j][3] = f2tf(ra3); al[j][3] = f2tf(ra3 - __uint_as_float(ah[j][3]));
            }

            // ---- stage gm1 + relu ----
            #pragma unroll
            for (int nt = 0; nt < 4; nt++) {
                int o0 = 8 * nt + 2 * t;
                float d0 = Tn[r0 * 36 + o0], d1 = Tn[r0 * 36 + o0 + 1];
                float d2 = Tn[r1 * 36 + o0], d3 = Tn[r1 * 36 + o0 + 1];
                #pragma unroll
                for (int kt = 0; kt < 4; kt++) {
                    mma8(d0, d1, d2, d3, ah[kt][0], ah[kt][1], ah[kt][2], ah[kt][3],
                         w1f[kt][nt][0], w1f[kt][nt][1]);
                    mma8(d0, d1, d2, d3, al[kt][0], al[kt][1], al[kt][2], al[kt][3],
                         w1f[kt][nt][0], w1f[kt][nt][1]);
                }
                dd[nt][0] = fmaxf(d0, 0.f); dd[nt][1] = fmaxf(d1, 0.f);
                dd[nt][2] = fmaxf(d2, 0.f); dd[nt][3] = fmaxf(d3, 0.f);
            }

            // ---- D->A transform ----
            #pragma unroll
            for (int j = 0; j < 4; j++) {
                float e0 = __shfl_sync(0xffffffffu, dd[j][0], s1l);
                float e1 = __shfl_sync(0xffffffffu, dd[j][1], s1l);
                float f0 = __shfl_sync(0xffffffffu, dd[j][0], s2l);
                float f1 = __shfl_sync(0xffffffffu, dd[j][1], s2l);
                float g0 = __shfl_sync(0xffffffffu, dd[j][2], s1l);
                float g1 = __shfl_sync(0xffffffffu, dd[j][3], s1l);
                float h0 = __shfl_sync(0xffffffffu, dd[j][2], s2l);
                float h1 = __shfl_sync(0xffffffffu, dd[j][3], s2l);
                float ra0 = odd ? e1 : e0;
                float ra2 = odd ? f1 : f0;
                float ra1 = odd ? g1 : g0;
                float ra3 = odd ? h1 : h0;
                ah[j][0] = f2tf(ra0); al[j][0] = f2tf(ra0 - __uint_as_float(ah[j][0]));
                ah[j][1] = f2tf(ra1); al[j][1] = f2tf(ra1 - __uint_as_float(ah[j][1]));
                ah[j][2] = f2tf(ra2); al[j][2] = f2tf(ra2 - __uint_as_float(ah[j][2]));
                ah[j][3] = f2tf(ra3); al[j][3] = f2tf(ra3 - __uint_as_float(ah[j][3]));
            }

            // ---- stage gm2 + relu/max fold ----
            #pragma unroll
            for (int nt = 0; nt < 4; nt++) {
                float d0 = ct2a[nt], d1 = ct2b[nt], d2 = ct2a[nt], d3 = ct2b[nt];
                #pragma unroll
                for (int kt = 0; kt < 4; kt++) {
                    mma8(d0, d1, d2, d3, ah[kt][0], ah[kt][1], ah[kt][2], ah[kt][3],
                         w2f[kt][nt][0], w2f[kt][nt][1]);
                    mma8(d0, d1, d2, d3, al[kt][0], al[kt][1], al[kt][2], al[kt][3],
                         w2f[kt][nt][0], w2f[kt][nt][1]);
                }
                mm[nt][0] = fmaxf(mm[nt][0], fmaxf(d0, d2));
                mm[nt][1] = fmaxf(mm[nt][1], fmaxf(d1, d3));
            }
        }

        // cross-lane max over the g bits (rows), then lanes 0..3 write
        #pragma unroll
        for (int nt = 0; nt < 4; nt++) {
            #pragma unroll
            for (int j = 0; j < 2; j++) {
                float v = mm[nt][j];
                v = fmaxf(v, __shfl_xor_sync(0xffffffffu, v, 4));
                v = fmaxf(v, __shfl_xor_sync(0xffffffffu, v, 8));
                v = fmaxf(v, __shfl_xor_sync(0xffffffffu, v, 16));
                mm[nt][j] = v;
            }
        }
        if (g == 0) {
            #pragma unroll
            for (int nt = 0; nt < 4; nt++) {
                int o0 = 8 * nt + 2 * t;
                size_t base = ((size_t)b * 32 + o0) * NM + mt * 32 + ml;
                g_gpool[base]      = mm[nt][0];
                g_gpool[base + NM] = mm[nt][1];
            }
        }
    }
}

// ---------------------------------------------------------------------------
// Kernel 2: cosine sim + argmax gather + MLP + final layers -> out
// (proven R7 version, 58.8us)
// ---------------------------------------------------------------------------
__global__ __launch_bounds__(256) void k_out(
    const float* __restrict__ x_label, const float* __restrict__ x_object,
    const float* __restrict__ template_xyz,
    const float* __restrict__ mlp_w1, const float* __restrict__ mlp_s1,
    const float* __restrict__ mlp_t1, const float* __restrict__ mlp_w2,
    const float* __restrict__ mlp_s2, const float* __restrict__ mlp_t2,
    const float* __restrict__ fl_w1, const float* __restrict__ fl_s1,
    const float* __restrict__ fl_t1, const float* __restrict__ fl_w2,
    const float* __restrict__ fl_b2, float* __restrict__ out)
{
    __shared__ float xo_s[32][64];
    __shared__ float w1T[68][32];
    __shared__ float w2T[32][32];
    __shared__ float na_s[64];
    __shared__ float hs[32][33];
    __shared__ float fu[64][33];
    __shared__ float o1s[64][33];
    __shared__ float sb[8][32];
    __shared__ int   si[8][32];

    const int b = blockIdx.x >> 2, mt = blockIdx.x & 3;
    const int tid = threadIdx.x, ml = tid & 31, p = tid >> 5;
    const int m = mt * 32 + ml;

    for (int i = tid; i < 2048; i += 256)
        ((float*)xo_s)[i] = x_object[(size_t)b * 2048 + i];
    for (int i = tid; i < 68 * 32; i += 256) {
        int j = i >> 5, o = i & 31;
        w1T[j][o] = mlp_w1[o * 68 + j];
    }
    for (int i = tid; i < 1024; i += 256) {
        int c = i >> 5, o = i & 31;
        w2T[c][o] = mlp_w2[o * 32 + c];
    }
    for (int i = tid; i < 1024; i += 256) {
        int c = i >> 5, q = i & 31;
        fu[32 + c][q] = g_gpool[((size_t)b * 32 + c) * NM + mt * 32 + q];
    }
    __syncthreads();
    if (tid < 64) {
        float s = 0.f;
        #pragma unroll
        for (int c = 0; c < 32; c++) { float v = xo_s[c][tid]; s += v * v; }
        na_s[tid] = sqrtf(s);
    }

    float xl[32];
    #pragma unroll
    for (int c = 0; c < 32; c++)
        xl[c] = x_label[(size_t)b * 4096 + c * 128 + m];
    float nb = 0.f;
    #pragma unroll
    for (int c = 0; c < 32; c++) nb += xl[c] * xl[c];
    nb = sqrtf(nb);
    __syncthreads();

    float best = -3.4e38f; int bidx = 8 * p;
    #pragma unroll 1
    for (int n = 8 * p; n < 8 * p + 8; n++) {
        float num = 0.f;
        #pragma unroll
        for (int c = 0; c < 32; c++) num += xo_s[c][n] * xl[c];
        float cs = num / fmaxf(na_s[n] * nb, 1e-8f);
        if (cs > best) { best = cs; bidx = n; }
    }
    sb[p][ml] = best; si[p][ml] = bidx;
    __syncthreads();
    best = sb[0][ml]; bidx = si[0][ml];
    #pragma unroll
    for (int pp = 1; pp < 8; pp++)
        if (sb[pp][ml] > best) { best = sb[pp][ml]; bidx = si[pp][ml]; }

    float hr[4];
    {
        const float* tx = template_xyz + (size_t)b * 192 + bidx * 3;
        float a0 = tx[0], a1 = tx[1], a2 = tx[2];
        #pragma unroll
        for (int oo = 0; oo < 4; oo++) {
            int o = 4 * p + oo;
            hr[oo] = w1T[0][o] * best + w1T[1][o] * a0 +
                     w1T[2][o] * a1 + w1T[3][o] * a2;
        }
    }
    #pragma unroll
    for (int c = 0; c < 32; c++) {
        float xoc = xo_s[c][bidx];
        #pragma unroll
        for (int oo = 0; oo < 4; oo++) hr[oo] += w1T[4 + c][4 * p + oo] * xoc;
    }
    #pragma unroll
    for (int c = 0; c < 32; c++) {
        float v = xl[c];
        #pragma unroll
        for (int oo = 0; oo < 4; oo++) hr[oo] += w1T[36 + c][4 * p + oo] * v;
    }
    #pragma unroll
    for (int oo = 0; oo < 4; oo++) {
        int o = 4 * p + oo;
        hs[ml][o] = fmaxf(mlp_s1[o] * hr[oo] + mlp_t1[o], 0.f);
    }
    __syncthreads();

    float h2r[4] = {0.f, 0.f, 0.f, 0.f};
    #pragma unroll
    for (int c = 0; c < 32; c++) {
        float v = hs[ml][c];
        #pragma unroll
        for (int oo = 0; oo < 4; oo++) h2r[oo] += w2T[c][4 * p + oo] * v;
    }
    #pragma unroll
    for (int oo = 0; oo < 4; oo++) {
        int o = 4 * p + oo;
        fu[o][ml] = fmaxf(mlp_s2[o] * h2r[oo] + mlp_t2[o], 0.f);
    }
    __syncthreads();

    float fv[64];
    #pragma unroll
    for (int c = 0; c < 64; c++) fv[c] = fu[c][ml];
    #pragma unroll 2
    for (int oo = 0; oo < 8; oo++) {
        int o = 8 * p + oo;
        float acc = 0.f;
        const float4* wp4 = (const float4*)(fl_w1 + o * 64);
        #pragma unroll
        for (int c4 = 0; c4 < 16; c4++) {
            float4 ww = __ldg(&wp4[c4]);
            acc += ww.x * fv[4 * c4] + ww.y * fv[4 * c4 + 1] +
                   ww.z * fv[4 * c4 + 2] + ww.w * fv[4 * c4 + 3];
        }
        o1s[o][ml] = fmaxf(fl_s1[o] * acc + fl_t1[o], 0.f);
    }
    __syncthreads();

    float ov[64];
    #pragma unroll
    for (int c = 0; c < 64; c++) ov[c] = o1s[c][ml];
    #pragma unroll 2
    for (int oo = 0; oo < 8; oo++) {
        int o = 8 * p + oo;
        float acc = fl_b2[o];
        const float4* wp4 = (const float4*)(fl_w2 + o * 64);
        #pragma unroll
        for (int c4 = 0; c4 < 16; c4++) {
            float4 ww = __ldg(&wp4[c4]);
            acc += ww.x * ov[4 * c4] + ww.y * ov[4 * c4 + 1] +
                   ww.z * ov[4 * c4 + 2] + ww.w * ov[4 * c4 + 3];
        }
        out[((size_t)b * 64 + o) * NM + m] = acc;
    }
}

extern "C" void kernel_launch(void* const* d_in, const int* in_sizes, int n_in,
                              void* d_out, int out_size)
{
    const float* x_label      = (const float*)d_in[0];
    const float* x_object     = (const float*)d_in[1];
    const float* template_xyz = (const float*)d_in[2];
    const float* mlp_w1 = (const float*)d_in[3];
    const float* mlp_s1 = (const float*)d_in[4];
    const float* mlp_t1 = (const float*)d_in[5];
    const float* mlp_w2 = (const float*)d_in[6];
    const float* mlp_s2 = (const float*)d_in[7];
    const float* mlp_t2 = (const float*)d_in[8];
    const float* gw_w1  = (const float*)d_in[9];
    const float* gw_b1  = (const float*)d_in[10];
    const float* gw_s   = (const float*)d_in[11];
    const float* gw_t   = (const float*)d_in[12];
    const float* gw_w2  = (const float*)d_in[13];
    const float* gw_b2  = (const float*)d_in[14];
    const float* gm_w1  = (const float*)d_in[15];
    const float* gm_s1  = (const float*)d_in[16];
    const float* gm_t1  = (const float*)d_in[17];
    const float* gm_w2  = (const float*)d_in[18];
    const float* gm_s2  = (const float*)d_in[19];
    const float* gm_t2  = (const float*)d_in[20];
    const float* fl_w1  = (const float*)d_in[21];
    const float* fl_s1  = (const float*)d_in[22];
    const float* fl_t1  = (const float*)d_in[23];
    const float* fl_w2  = (const float*)d_in[24];
    const float* fl_b2  = (const float*)d_in[25];

    k_gpool<<<512, 128>>>(x_label, x_object, template_xyz,
                          gw_w1, gw_b1, gw_s, gw_t, gw_w2, gw_b2,
                          gm_w1, gm_s1, gm_t1, gm_w2, gm_s2, gm_t2);
    k_out<<<512, 256>>>(x_label, x_object, template_xyz,
                        mlp_w1, mlp_s1, mlp_t1, mlp_w2, mlp_s2, mlp_t2,
                        fl_w1, fl_s1, fl_t1, fl_w2, fl_b2, (float*)d_out);
}

// round 14
// speedup vs baseline: 1.8347x; 1.0538x over previous
#include <cuda_runtime.h>

#define BB 128
#define NM 128

__device__ __forceinline__ unsigned f2tf(float x) {
    unsigned u; asm("cvt.rna.tf32.f32 %0, %1;" : "=r"(u) : "f"(x)); return u;
}
__device__ __forceinline__ void mma8(float& d0, float& d1, float& d2, float& d3,
                                     unsigned a0, unsigned a1, unsigned a2, unsigned a3,
                                     unsigned b0, unsigned b1) {
    asm("mma.sync.aligned.m16n8k8.row.col.f32.tf32.tf32.f32 "
        "{%0,%1,%2,%3},{%4,%5,%6,%7},{%8,%9},{%0,%1,%2,%3};"
        : "+f"(d0), "+f"(d1), "+f"(d2), "+f"(d3)
        : "r"(a0), "r"(a1), "r"(a2), "r"(a3), "r"(b0), "r"(b1));
}

// ---------------------------------------------------------------------------
// Fused kernel: tf32-MMA gpool (R13 form, ~110us) + cos/argmax/MLP/final
// layers (R12 phase layout). grid 512 = B*4 m-tiles of 32; block 128.
// Smem arena 9088 floats (36,352 B), phase-disjoint aliasing:
//   gpool:  xoT[0..2304) Bn[2304..4608) Tn[4608..6912) As[6912..8064)
//           xls[8064..9088) -> gps (gpool tile) after xls dies
//   k_out:  w1T[2304..4480) w2T[4480..5504) na_s[5504..5568)
//           sb[5568..5696) si[5696..5824) hs[5824..6880) fuh2[6912..7968)
//           o1s[2304..4416) over dead w1T
// ---------------------------------------------------------------------------
__global__ __launch_bounds__(128) void k_fused(
    const float* __restrict__ x_label, const float* __restrict__ x_object,
    const float* __restrict__ template_xyz,
    const float* __restrict__ mlp_w1, const float* __restrict__ mlp_s1,
    const float* __restrict__ mlp_t1, const float* __restrict__ mlp_w2,
    const float* __restrict__ mlp_s2, const float* __restrict__ mlp_t2,
    const float* __restrict__ gw_w1, const float* __restrict__ gw_b1,
    const float* __restrict__ gw_s,  const float* __restrict__ gw_t,
    const float* __restrict__ gw_w2, const float* __restrict__ gw_b2,
    const float* __restrict__ gm_w1, const float* __restrict__ gm_s1,
    const float* __restrict__ gm_t1, const float* __restrict__ gm_w2,
    const float* __restrict__ gm_s2, const float* __restrict__ gm_t2,
    const float* __restrict__ fl_w1, const float* __restrict__ fl_s1,
    const float* __restrict__ fl_t1, const float* __restrict__ fl_w2,
    const float* __restrict__ fl_b2, float* __restrict__ out)
{
    __shared__ __align__(16) float S[9088];

    float* xoT = S;             // [64][36]
    float* Bn  = S + 2304;      // [64][36]
    float* Tn  = S + 4608;      // [64][36]
    float* As  = S + 6912;      // [32][36]
    float* xls = S + 8064;      // [32][32]; gps alias after death
    float* gps = S + 8064;      // [32][32] gpool result tile

    const int tid = threadIdx.x;
    const int b = blockIdx.x >> 2, mt = blockIdx.x & 3;

    // ============== gpool: stage inputs ==============
    for (int i = tid; i < 2048; i += 128) {
        int c = i >> 6, n = i & 63;
        xoT[n * 36 + c] = x_object[(size_t)b * 2048 + i];
    }
    for (int i = tid; i < 1024; i += 128) {
        int c = i >> 5, ml = i & 31;
        xls[c * 32 + ml] = x_label[(size_t)b * 4096 + c * 128 + mt * 32 + ml];
    }
    __syncthreads();

    // ============== gpool: precompute ==============
    for (int i = tid; i < 2048; i += 128) {
        int o = i >> 6, n = i & 63;
        float a = 0.f;
        #pragma unroll
        for (int c = 0; c < 32; c++) a += gw_w1[o * 32 + c] * xoT[n * 36 + c];
        Bn[n * 36 + o] = -gw_s[o] * a;
        const float* tx = template_xyz + (size_t)b * 192 + n * 3;
        Tn[n * 36 + o] = gm_s1[o] * (gm_w1[o * 35] * tx[0] + gm_w1[o * 35 + 1] * tx[1] +
                                     gm_w1[o * 35 + 2] * tx[2]) + gm_t1[o];
    }
    for (int i = tid; i < 1024; i += 128) {
        int o = i >> 5, ml = i & 31;
        float a = 0.f;
        #pragma unroll
        for (int c = 0; c < 32; c++) a += gw_w1[o * 32 + c] * xls[c * 32 + ml];
        As[ml * 36 + o] = gw_s[o] * a + gw_s[o] * gw_b1[o] + gw_t[o];
    }

    // ---- per-lane weight fragments (tf32, B col-major) ----
    const int w = tid >> 5, lane = tid & 31;
    const int g = lane >> 2, t = lane & 3;

    unsigned w0[4][4][2], w1f[4][4][2], w2f[4][4][2];
    float b2a[4], b2b[4], ct2a[4], ct2b[4];
    #pragma unroll
    for (int nt = 0; nt < 4; nt++) {
        int no = 8 * nt + g;
        float s1v = gm_s1[no], s2v = gm_s2[no];
        #pragma unroll
        for (int kt = 0; kt < 4; kt++) {
            int k0 = 8 * kt + t;
            w0[kt][nt][0]  = f2tf(gw_w2[no * 32 + k0]);
            w0[kt][nt][1]  = f2tf(gw_w2[no * 32 + k0 + 4]);
            w1f[kt][nt][0] = f2tf(s1v * gm_w1[no * 35 + 3 + k0]);
            w1f[kt][nt][1] = f2tf(s1v * gm_w1[no * 35 + 3 + k0 + 4]);
            w2f[kt][nt][0] = f2tf(s2v * gm_w2[no * 32 + k0]);
            w2f[kt][nt][1] = f2tf(s2v * gm_w2[no * 32 + k0 + 4]);
        }
        b2a[nt]  = gw_b2[8 * nt + 2 * t];
        b2b[nt]  = gw_b2[8 * nt + 2 * t + 1];
        ct2a[nt] = gm_t2[8 * nt + 2 * t];
        ct2b[nt] = gm_t2[8 * nt + 2 * t + 1];
    }
    __syncthreads();   // As ready; xls dead -> gps region live for writes

    const int s1l = (lane & ~3) | (t >> 1);
    const int s2l = s1l + 2;
    const bool odd = (t & 1) != 0;

    // ============== gpool main loop (tf32 MMA cascade) ==============
    #pragma unroll 1
    for (int mi = 0; mi < 8; mi++) {
        const int ml = w * 8 + mi;
        float asv[8];
        #pragma unroll
        for (int kt = 0; kt < 4; kt++) {
            asv[2 * kt]     = As[ml * 36 + 8 * kt + t];
            asv[2 * kt + 1] = As[ml * 36 + 8 * kt + t + 4];
        }
        float mm[4][2];
        #pragma unroll
        for (int nt = 0; nt < 4; nt++) { mm[nt][0] = 0.f; mm[nt][1] = 0.f; }

        #pragma unroll 1
        for (int r = 0; r < 4; r++) {
            const int r0 = 16 * r + g, r1 = r0 + 8;

            unsigned ah[4][4], al[4][4];
            #pragma unroll
            for (int kt = 0; kt < 4; kt++) {
                int c0 = 8 * kt + t, c1 = c0 + 4;
                float x00 = asv[2 * kt]     + Bn[r0 * 36 + c0];
                float x10 = asv[2 * kt]     + Bn[r1 * 36 + c0];
                float x01 = asv[2 * kt + 1] + Bn[r0 * 36 + c1];
                float x11 = asv[2 * kt + 1] + Bn[r1 * 36 + c1];
                x00 = fmaxf(x00, 0.2f * x00); x10 = fmaxf(x10, 0.2f * x10);
                x01 = fmaxf(x01, 0.2f * x01); x11 = fmaxf(x11, 0.2f * x11);
                ah[kt][0] = f2tf(x00); al[kt][0] = f2tf(x00 - __uint_as_float(ah[kt][0]));
                ah[kt][1] = f2tf(x10); al[kt][1] = f2tf(x10 - __uint_as_float(ah[kt][1]));
                ah[kt][2] = f2tf(x01); al[kt][2] = f2tf(x01 - __uint_as_float(ah[kt][2]));
                ah[kt][3] = f2tf(x11); al[kt][3] = f2tf(x11 - __uint_as_float(ah[kt][3]));
            }

            float dd[4][4];
            #pragma unroll
            for (int nt = 0; nt < 4; nt++) {
                float d0 = b2a[nt], d1 = b2b[nt], d2 = b2a[nt], d3 = b2b[nt];
                #pragma unroll
                for (int kt = 0; kt < 4; kt++) {
                    mma8(d0, d1, d2, d3, ah[kt][0], ah[kt][1], ah[kt][2], ah[kt][3],
                         w0[kt][nt][0], w0[kt][nt][1]);
                    mma8(d0, d1, d2, d3, al[kt][0], al[kt][1], al[kt][2], al[kt][3],
                         w0[kt][nt][0], w0[kt][nt][1]);
                }
                int o0 = 8 * nt + 2 * t;
                dd[nt][0] = __fdividef(xoT[r0 * 36 + o0],     1.f + __expf(-d0));
                dd[nt][1] = __fdividef(xoT[r0 * 36 + o0 + 1], 1.f + __expf(-d1));
                dd[nt][2] = __fdividef(xoT[r1 * 36 + o0],     1.f + __expf(-d2));
                dd[nt][3] = __fdividef(xoT[r1 * 36 + o0 + 1], 1.f + __expf(-d3));
            }

            #pragma unroll
            for (int j = 0; j < 4; j++) {
                float e0 = __shfl_sync(0xffffffffu, dd[j][0], s1l);
                float e1 = __shfl_sync(0xffffffffu, dd[j][1], s1l);
                float f0 = __shfl_sync(0xffffffffu, dd[j][0], s2l);
                float f1 = __shfl_sync(0xffffffffu, dd[j][1], s2l);
                float g0 = __shfl_sync(0xffffffffu, dd[j][2], s1l);
                float g1 = __shfl_sync(0xffffffffu, dd[j][3], s1l);
                float h0 = __shfl_sync(0xffffffffu, dd[j][2], s2l);
                float h1 = __shfl_sync(0xffffffffu, dd[j][3], s2l);
                float ra0 = odd ? e1 : e0;
                float ra2 = odd ? f1 : f0;
                float ra1 = odd ? g1 : g0;
                float ra3 = odd ? h1 : h0;
                ah[j][0] = f2tf(ra0); al[j][0] = f2tf(ra0 - __uint_as_float(ah[j][0]));
                ah[j][1] = f2tf(ra1); al[j][1] = f2tf(ra1 - __uint_as_float(ah[j][1]));
                ah[j][2] = f2tf(ra2); al[j][2] = f2tf(ra2 - __uint_as_float(ah[j][2]));
                ah[j][3] = f2tf(ra3); al[j][3] = f2tf(ra3 - __uint_as_float(ah[j][3]));
            }

            #pragma unroll
            for (int nt = 0; nt < 4; nt++) {
                int o0 = 8 * nt + 2 * t;
                float d0 = Tn[r0 * 36 + o0], d1 = Tn[r0 * 36 + o0 + 1];
                float d2 = Tn[r1 * 36 + o0], d3 = Tn[r1 * 36 + o0 + 1];
                #pragma unroll
                for (int kt = 0; kt < 4; kt++) {
                    mma8(d0, d1, d2, d3, ah[kt][0], ah[kt][1], ah[kt][2], ah[kt][3],
                         w1f[kt][nt][0], w1f[kt][nt][1]);
                    mma8(d0, d1, d2, d3, al[kt][0], al[kt][1], al[kt][2], al[kt][3],
                         w1f[kt][nt][0], w1f[kt][nt][1]);
                }
                dd[nt][0] = fmaxf(d0, 0.f); dd[nt][1] = fmaxf(d1, 0.f);
                dd[nt][2] = fmaxf(d2, 0.f); dd[nt][3] = fmaxf(d3, 0.f);
            }

            #pragma unroll
            for (int j = 0; j < 4; j++) {
                float e0 = __shfl_sync(0xffffffffu, dd[j][0], s1l);
                float e1 = __shfl_sync(0xffffffffu, dd[j][1], s1l);
                float f0 = __shfl_sync(0xffffffffu, dd[j][0], s2l);
                float f1 = __shfl_sync(0xffffffffu, dd[j][1], s2l);
                float g0 = __shfl_sync(0xffffffffu, dd[j][2], s1l);
                float g1 = __shfl_sync(0xffffffffu, dd[j][3], s1l);
                float h0 = __shfl_sync(0xffffffffu, dd[j][2], s2l);
                float h1 = __shfl_sync(0xffffffffu, dd[j][3], s2l);
                float ra0 = odd ? e1 : e0;
                float ra2 = odd ? f1 : f0;
                float ra1 = odd ? g1 : g0;
                float ra3 = odd ? h1 : h0;
                ah[j][0] = f2tf(ra0); al[j][0] = f2tf(ra0 - __uint_as_float(ah[j][0]));
                ah[j][1] = f2tf(ra1); al[j][1] = f2tf(ra1 - __uint_as_float(ah[j][1]));
                ah[j][2] = f2tf(ra2); al[j][2] = f2tf(ra2 - __uint_as_float(ah[j][2]));
                ah[j][3] = f2tf(ra3); al[j][3] = f2tf(ra3 - __uint_as_float(ah[j][3]));
            }

            #pragma unroll
            for (int nt = 0; nt < 4; nt++) {
                float d0 = ct2a[nt], d1 = ct2b[nt], d2 = ct2a[nt], d3 = ct2b[nt];
                #pragma unroll
                for (int kt = 0; kt < 4; kt++) {
                    mma8(d0, d1, d2, d3, ah[kt][0], ah[kt][1], ah[kt][2], ah[kt][3],
                         w2f[kt][nt][0], w2f[kt][nt][1]);
                    mma8(d0, d1, d2, d3, al[kt][0], al[kt][1], al[kt][2], al[kt][3],
                         w2f[kt][nt][0], w2f[kt][nt][1]);
                }
                mm[nt][0] = fmaxf(mm[nt][0], fmaxf(d0, d2));
                mm[nt][1] = fmaxf(mm[nt][1], fmaxf(d1, d3));
            }
        }

        #pragma unroll
        for (int nt = 0; nt < 4; nt++) {
            #pragma unroll
            for (int j = 0; j < 2; j++) {
                float v = mm[nt][j];
                v = fmaxf(v, __shfl_xor_sync(0xffffffffu, v, 4));
                v = fmaxf(v, __shfl_xor_sync(0xffffffffu, v, 8));
                v = fmaxf(v, __shfl_xor_sync(0xffffffffu, v, 16));
                mm[nt][j] = v;
            }
        }
        if (g == 0) {
            #pragma unroll
            for (int nt = 0; nt < 4; nt++) {
                int o0 = 8 * nt + 2 * t;
                gps[o0 * 32 + ml]       = mm[nt][0];
                gps[(o0 + 1) * 32 + ml] = mm[nt][1];
            }
        }
    }
    __syncthreads();   // gpool done; Bn/Tn/As dead

    // ============== k_out phase staging ==============
    float* w1T  = S + 2304;          // [68][32]
    float* w2T  = S + 4480;          // [32][32]
    float* na_s = S + 5504;          // [64]
    float* sb   = S + 5568;          // [4][32]
    int*   si   = (int*)(S + 5696);  // [4][32]
    float* hs   = S + 5824;          // [32][33]
    float* fuh2 = S + 6912;          // [32][33]
    float* o1s  = S + 2304;          // [64][33] over dead w1T

    for (int i = tid; i < 2176; i += 128) {
        int j = i >> 5, oo = i & 31;
        w1T[j * 32 + oo] = mlp_w1[oo * 68 + j];
    }
    for (int i = tid; i < 1024; i += 128) {
        int c = i >> 5, oo = i & 31;
        w2T[c * 32 + oo] = mlp_w2[oo * 32 + c];
    }
    if (tid < 64) {
        float s = 0.f;
        #pragma unroll
        for (int c = 0; c < 32; c++) { float v = xoT[tid * 36 + c]; s += v * v; }
        na_s[tid] = sqrtf(s);
    }

    const int ml = tid & 31, p = tid >> 5;
    const int m = mt * 32 + ml;

    float xl[32];
    #pragma unroll
    for (int c = 0; c < 32; c++)
        xl[c] = x_label[(size_t)b * 4096 + c * 128 + m];
    float nb = 0.f;
    #pragma unroll
    for (int c = 0; c < 32; c++) nb += xl[c] * xl[c];
    nb = sqrtf(nb);
    __syncthreads();

    // argmax (n split across 4 parts, first-max semantics preserved)
    float best = -3.4e38f; int bidx = 16 * p;
    #pragma unroll 1
    for (int n = 16 * p; n < 16 * p + 16; n++) {
        float num = 0.f;
        #pragma unroll
        for (int c = 0; c < 32; c++) num += xoT[n * 36 + c] * xl[c];
        float cs = num / fmaxf(na_s[n] * nb, 1e-8f);
        if (cs > best) { best = cs; bidx = n; }
    }
    sb[p * 32 + ml] = best; si[p * 32 + ml] = bidx;
    __syncthreads();
    best = sb[ml]; bidx = si[ml];
    #pragma unroll
    for (int pp = 1; pp < 4; pp++) {
        if (sb[pp * 32 + ml] > best) { best = sb[pp * 32 + ml]; bidx = si[pp * 32 + ml]; }
    }

    // MLP layer 1 (o in [8p, 8p+8))
    float hr[8];
    {
        const float* tx = template_xyz + (size_t)b * 192 + bidx * 3;
        float a0 = tx[0], a1 = tx[1], a2 = tx[2];
        #pragma unroll
        for (int oo = 0; oo < 8; oo++) {
            int oc = 8 * p + oo;
            hr[oo] = w1T[0 * 32 + oc] * best + w1T[1 * 32 + oc] * a0 +
                     w1T[2 * 32 + oc] * a1 + w1T[3 * 32 + oc] * a2;
        }
    }
    #pragma unroll
    for (int c = 0; c < 32; c++) {
        float xoc = xoT[bidx * 36 + c];
        #pragma unroll
        for (int oo = 0; oo < 8; oo++) hr[oo] += w1T[(4 + c) * 32 + 8 * p + oo] * xoc;
    }
    #pragma unroll
    for (int c = 0; c < 32; c++) {
        float v = xl[c];
        #pragma unroll
        for (int oo = 0; oo < 8; oo++) hr[oo] += w1T[(36 + c) * 32 + 8 * p + oo] * v;
    }
    #pragma unroll
    for (int oo = 0; oo < 8; oo++) {
        int oc = 8 * p + oo;
        hs[ml * 33 + oc] = fmaxf(mlp_s1[oc] * hr[oo] + mlp_t1[oc], 0.f);
    }
    __syncthreads();

    // MLP layer 2 -> fuh2
    float h2r[8] = {0.f, 0.f, 0.f, 0.f, 0.f, 0.f, 0.f, 0.f};
    #pragma unroll
    for (int c = 0; c < 32; c++) {
        float v = hs[ml * 33 + c];
        #pragma unroll
        for (int oo = 0; oo < 8; oo++) h2r[oo] += w2T[c * 32 + 8 * p + oo] * v;
    }
    #pragma unroll
    for (int oo = 0; oo < 8; oo++) {
        int oc = 8 * p + oo;
        fuh2[oc * 33 + ml] = fmaxf(mlp_s2[oc] * h2r[oo] + mlp_t2[oc], 0.f);
    }
    __syncthreads();

    // fl1 (o in [16p, 16p+16))
    float fv[64];
    #pragma unroll
    for (int c = 0; c < 32; c++) fv[c] = fuh2[c * 33 + ml];
    #pragma unroll
    for (int c = 0; c < 32; c++) fv[32 + c] = gps[c * 32 + ml];
    #pragma unroll 4
    for (int oo = 0; oo < 16; oo++) {
        int oc = 16 * p + oo;
        float acc = 0.f;
        const float4* wp4 = (const float4*)(fl_w1 + oc * 64);
        #pragma unroll
        for (int c4 = 0; c4 < 16; c4++) {
            float4 ww = __ldg(&wp4[c4]);
            acc += ww.x * fv[4 * c4] + ww.y * fv[4 * c4 + 1] +
                   ww.z * fv[4 * c4 + 2] + ww.w * fv[4 * c4 + 3];
        }
        o1s[oc * 33 + ml] = fmaxf(fl_s1[oc] * acc + fl_t1[oc], 0.f);
    }
    __syncthreads();

    // fl2
    float ov[64];
    #pragma unroll
    for (int c = 0; c < 64; c++) ov[c] = o1s[c * 33 + ml];
    #pragma unroll 4
    for (int oo = 0; oo < 16; oo++) {
        int oc = 16 * p + oo;
        float acc = fl_b2[oc];
        const float4* wp4 = (const float4*)(fl_w2 + oc * 64);
        #pragma unroll
        for (int c4 = 0; c4 < 16; c4++) {
            float4 ww = __ldg(&wp4[c4]);
            acc += ww.x * ov[4 * c4] + ww.y * ov[4 * c4 + 1] +
                   ww.z * ov[4 * c4 + 2] + ww.w * ov[4 * c4 + 3];
        }
        out[((size_t)b * 64 + oc) * NM + m] = acc;
    }
}

extern "C" void kernel_launch(void* const* d_in, const int* in_sizes, int n_in,
                              void* d_out, int out_size)
{
    const float* x_label      = (const float*)d_in[0];
    const float* x_object     = (const float*)d_in[1];
    const float* template_xyz = (const float*)d_in[2];
    const float* mlp_w1 = (const float*)d_in[3];
    const float* mlp_s1 = (const float*)d_in[4];
    const float* mlp_t1 = (const float*)d_in[5];
    const float* mlp_w2 = (const float*)d_in[6];
    const float* mlp_s2 = (const float*)d_in[7];
    const float* mlp_t2 = (const float*)d_in[8];
    const float* gw_w1  = (const float*)d_in[9];
    const float* gw_b1  = (const float*)d_in[10];
    const float* gw_s   = (const float*)d_in[11];
    const float* gw_t   = (const float*)d_in[12];
    const float* gw_w2  = (const float*)d_in[13];
    const float* gw_b2  = (const float*)d_in[14];
    const float* gm_w1  = (const float*)d_in[15];
    const float* gm_s1  = (const float*)d_in[16];
    const float* gm_t1  = (const float*)d_in[17];
    const float* gm_w2  = (const float*)d_in[18];
    const float* gm_s2  = (const float*)d_in[19];
    const float* gm_t2  = (const float*)d_in[20];
    const float* fl_w1  = (const float*)d_in[21];
    const float* fl_s1  = (const float*)d_in[22];
    const float* fl_t1  = (const float*)d_in[23];
    const float* fl_w2  = (const float*)d_in[24];
    const float* fl_b2  = (const float*)d_in[25];

    k_fused<<<512, 128>>>(x_label, x_object, template_xyz,
                          mlp_w1, mlp_s1, mlp_t1, mlp_w2, mlp_s2, mlp_t2,
                          gw_w1, gw_b1, gw_s, gw_t, gw_w2, gw_b2,
                          gm_w1, gm_s1, gm_t1, gm_w2, gm_s2, gm_t2,
                          fl_w1, fl_s1, fl_t1, fl_w2, fl_b2, (float*)d_out);
}

// round 15
// speedup vs baseline: 2.3435x; 1.2773x over previous
#include <cuda_runtime.h>

#define BB 128
#define NM 128

__device__ __forceinline__ unsigned f2tf(float x) {
    unsigned u; asm("cvt.rna.tf32.f32 %0, %1;" : "=r"(u) : "f"(x)); return u;
}
__device__ __forceinline__ void mma8(float& d0, float& d1, float& d2, float& d3,
                                     unsigned a0, unsigned a1, unsigned a2, unsigned a3,
                                     unsigned b0, unsigned b1) {
    asm("mma.sync.aligned.m16n8k8.row.col.f32.tf32.tf32.f32 "
        "{%0,%1,%2,%3},{%4,%5,%6,%7},{%8,%9},{%0,%1,%2,%3};"
        : "+f"(d0), "+f"(d1), "+f"(d2), "+f"(d3)
        : "r"(a0), "r"(a1), "r"(a2), "r"(a3), "r"(b0), "r"(b1));
}

// ---------------------------------------------------------------------------
// Fused kernel: tf32-MMA gpool + cos/argmax/MLP/final layers.
// R14 structure, with the hi/lo activation split REMOVED (single rna-rounded
// tf32 MMA per tile): 48 MMAs + ~48 cvt per 16-pixel chunk instead of 96+144.
// ---------------------------------------------------------------------------
__global__ __launch_bounds__(128) void k_fused(
    const float* __restrict__ x_label, const float* __restrict__ x_object,
    const float* __restrict__ template_xyz,
    const float* __restrict__ mlp_w1, const float* __restrict__ mlp_s1,
    const float* __restrict__ mlp_t1, const float* __restrict__ mlp_w2,
    const float* __restrict__ mlp_s2, const float* __restrict__ mlp_t2,
    const float* __restrict__ gw_w1, const float* __restrict__ gw_b1,
    const float* __restrict__ gw_s,  const float* __restrict__ gw_t,
    const float* __restrict__ gw_w2, const float* __restrict__ gw_b2,
    const float* __restrict__ gm_w1, const float* __restrict__ gm_s1,
    const float* __restrict__ gm_t1, const float* __restrict__ gm_w2,
    const float* __restrict__ gm_s2, const float* __restrict__ gm_t2,
    const float* __restrict__ fl_w1, const float* __restrict__ fl_s1,
    const float* __restrict__ fl_t1, const float* __restrict__ fl_w2,
    const float* __restrict__ fl_b2, float* __restrict__ out)
{
    __shared__ __align__(16) float S[9088];

    float* xoT = S;             // [64][36]
    float* Bn  = S + 2304;      // [64][36]
    float* Tn  = S + 4608;      // [64][36]
    float* As  = S + 6912;      // [32][36]
    float* xls = S + 8064;      // [32][32]; gps alias after death
    float* gps = S + 8064;      // [32][32] gpool result tile

    const int tid = threadIdx.x;
    const int b = blockIdx.x >> 2, mt = blockIdx.x & 3;

    // ============== gpool: stage inputs ==============
    for (int i = tid; i < 2048; i += 128) {
        int c = i >> 6, n = i & 63;
        xoT[n * 36 + c] = x_object[(size_t)b * 2048 + i];
    }
    for (int i = tid; i < 1024; i += 128) {
        int c = i >> 5, ml = i & 31;
        xls[c * 32 + ml] = x_label[(size_t)b * 4096 + c * 128 + mt * 32 + ml];
    }
    __syncthreads();

    // ============== gpool: precompute ==============
    for (int i = tid; i < 2048; i += 128) {
        int o = i >> 6, n = i & 63;
        float a = 0.f;
        #pragma unroll
        for (int c = 0; c < 32; c++) a += gw_w1[o * 32 + c] * xoT[n * 36 + c];
        Bn[n * 36 + o] = -gw_s[o] * a;
        const float* tx = template_xyz + (size_t)b * 192 + n * 3;
        Tn[n * 36 + o] = gm_s1[o] * (gm_w1[o * 35] * tx[0] + gm_w1[o * 35 + 1] * tx[1] +
                                     gm_w1[o * 35 + 2] * tx[2]) + gm_t1[o];
    }
    for (int i = tid; i < 1024; i += 128) {
        int o = i >> 5, ml = i & 31;
        float a = 0.f;
        #pragma unroll
        for (int c = 0; c < 32; c++) a += gw_w1[o * 32 + c] * xls[c * 32 + ml];
        As[ml * 36 + o] = gw_s[o] * a + gw_s[o] * gw_b1[o] + gw_t[o];
    }

    // ---- per-lane weight fragments (tf32, B col-major) ----
    const int w = tid >> 5, lane = tid & 31;
    const int g = lane >> 2, t = lane & 3;

    unsigned w0[4][4][2], w1f[4][4][2], w2f[4][4][2];
    float b2a[4], b2b[4], ct2a[4], ct2b[4];
    #pragma unroll
    for (int nt = 0; nt < 4; nt++) {
        int no = 8 * nt + g;
        float s1v = gm_s1[no], s2v = gm_s2[no];
        #pragma unroll
        for (int kt = 0; kt < 4; kt++) {
            int k0 = 8 * kt + t;
            w0[kt][nt][0]  = f2tf(gw_w2[no * 32 + k0]);
            w0[kt][nt][1]  = f2tf(gw_w2[no * 32 + k0 + 4]);
            w1f[kt][nt][0] = f2tf(s1v * gm_w1[no * 35 + 3 + k0]);
            w1f[kt][nt][1] = f2tf(s1v * gm_w1[no * 35 + 3 + k0 + 4]);
            w2f[kt][nt][0] = f2tf(s2v * gm_w2[no * 32 + k0]);
            w2f[kt][nt][1] = f2tf(s2v * gm_w2[no * 32 + k0 + 4]);
        }
        b2a[nt]  = gw_b2[8 * nt + 2 * t];
        b2b[nt]  = gw_b2[8 * nt + 2 * t + 1];
        ct2a[nt] = gm_t2[8 * nt + 2 * t];
        ct2b[nt] = gm_t2[8 * nt + 2 * t + 1];
    }
    __syncthreads();   // As ready; xls dead -> gps region live

    const int s1l = (lane & ~3) | (t >> 1);
    const int s2l = s1l + 2;
    const bool odd = (t & 1) != 0;

    // ============== gpool main loop (tf32 MMA cascade) ==============
    #pragma unroll 1
    for (int mi = 0; mi < 8; mi++) {
        const int ml = w * 8 + mi;
        float asv[8];
        #pragma unroll
        for (int kt = 0; kt < 4; kt++) {
            asv[2 * kt]     = As[ml * 36 + 8 * kt + t];
            asv[2 * kt + 1] = As[ml * 36 + 8 * kt + t + 4];
        }
        float mm[4][2];
        #pragma unroll
        for (int nt = 0; nt < 4; nt++) { mm[nt][0] = 0.f; mm[nt][1] = 0.f; }

        #pragma unroll 1
        for (int r = 0; r < 4; r++) {
            const int r0 = 16 * r + g, r1 = r0 + 8;

            unsigned ah[4][4];
            #pragma unroll
            for (int kt = 0; kt < 4; kt++) {
                int c0 = 8 * kt + t, c1 = c0 + 4;
                float x00 = asv[2 * kt]     + Bn[r0 * 36 + c0];
                float x10 = asv[2 * kt]     + Bn[r1 * 36 + c0];
                float x01 = asv[2 * kt + 1] + Bn[r0 * 36 + c1];
                float x11 = asv[2 * kt + 1] + Bn[r1 * 36 + c1];
                ah[kt][0] = f2tf(fmaxf(x00, 0.2f * x00));
                ah[kt][1] = f2tf(fmaxf(x10, 0.2f * x10));
                ah[kt][2] = f2tf(fmaxf(x01, 0.2f * x01));
                ah[kt][3] = f2tf(fmaxf(x11, 0.2f * x11));
            }

            float dd[4][4];
            #pragma unroll
            for (int nt = 0; nt < 4; nt++) {
                float d0 = b2a[nt], d1 = b2b[nt], d2 = b2a[nt], d3 = b2b[nt];
                #pragma unroll
                for (int kt = 0; kt < 4; kt++) {
                    mma8(d0, d1, d2, d3, ah[kt][0], ah[kt][1], ah[kt][2], ah[kt][3],
                         w0[kt][nt][0], w0[kt][nt][1]);
                }
                int o0 = 8 * nt + 2 * t;
                dd[nt][0] = __fdividef(xoT[r0 * 36 + o0],     1.f + __expf(-d0));
                dd[nt][1] = __fdividef(xoT[r0 * 36 + o0 + 1], 1.f + __expf(-d1));
                dd[nt][2] = __fdividef(xoT[r1 * 36 + o0],     1.f + __expf(-d2));
                dd[nt][3] = __fdividef(xoT[r1 * 36 + o0 + 1], 1.f + __expf(-d3));
            }

            #pragma unroll
            for (int j = 0; j < 4; j++) {
                float e0 = __shfl_sync(0xffffffffu, dd[j][0], s1l);
                float e1 = __shfl_sync(0xffffffffu, dd[j][1], s1l);
                float f0 = __shfl_sync(0xffffffffu, dd[j][0], s2l);
                float f1 = __shfl_sync(0xffffffffu, dd[j][1], s2l);
                float g0 = __shfl_sync(0xffffffffu, dd[j][2], s1l);
                float g1 = __shfl_sync(0xffffffffu, dd[j][3], s1l);
                float h0 = __shfl_sync(0xffffffffu, dd[j][2], s2l);
                float h1 = __shfl_sync(0xffffffffu, dd[j][3], s2l);
                ah[j][0] = f2tf(odd ? e1 : e0);
                ah[j][1] = f2tf(odd ? g1 : g0);
                ah[j][2] = f2tf(odd ? f1 : f0);
                ah[j][3] = f2tf(odd ? h1 : h0);
            }

            #pragma unroll
            for (int nt = 0; nt < 4; nt++) {
                int o0 = 8 * nt + 2 * t;
                float d0 = Tn[r0 * 36 + o0], d1 = Tn[r0 * 36 + o0 + 1];
                float d2 = Tn[r1 * 36 + o0], d3 = Tn[r1 * 36 + o0 + 1];
                #pragma unroll
                for (int kt = 0; kt < 4; kt++) {
                    mma8(d0, d1, d2, d3, ah[kt][0], ah[kt][1], ah[kt][2], ah[kt][3],
                         w1f[kt][nt][0], w1f[kt][nt][1]);
                }
                dd[nt][0] = fmaxf(d0, 0.f); dd[nt][1] = fmaxf(d1, 0.f);
                dd[nt][2] = fmaxf(d2, 0.f); dd[nt][3] = fmaxf(d3, 0.f);
            }

            #pragma unroll
            for (int j = 0; j < 4; j++) {
                float e0 = __shfl_sync(0xffffffffu, dd[j][0], s1l);
                float e1 = __shfl_sync(0xffffffffu, dd[j][1], s1l);
                float f0 = __shfl_sync(0xffffffffu, dd[j][0], s2l);
                float f1 = __shfl_sync(0xffffffffu, dd[j][1], s2l);
                float g0 = __shfl_sync(0xffffffffu, dd[j][2], s1l);
                float g1 = __shfl_sync(0xffffffffu, dd[j][3], s1l);
                float h0 = __shfl_sync(0xffffffffu, dd[j][2], s2l);
                float h1 = __shfl_sync(0xffffffffu, dd[j][3], s2l);
                ah[j][0] = f2tf(odd ? e1 : e0);
                ah[j][1] = f2tf(odd ? g1 : g0);
                ah[j][2] = f2tf(odd ? f1 : f0);
                ah[j][3] = f2tf(odd ? h1 : h0);
            }

            #pragma unroll
            for (int nt = 0; nt < 4; nt++) {
                float d0 = ct2a[nt], d1 = ct2b[nt], d2 = ct2a[nt], d3 = ct2b[nt];
                #pragma unroll
                for (int kt = 0; kt < 4; kt++) {
                    mma8(d0, d1, d2, d3, ah[kt][0], ah[kt][1], ah[kt][2], ah[kt][3],
                         w2f[kt][nt][0], w2f[kt][nt][1]);
                }
                mm[nt][0] = fmaxf(mm[nt][0], fmaxf(d0, d2));
                mm[nt][1] = fmaxf(mm[nt][1], fmaxf(d1, d3));
            }
        }

        #pragma unroll
        for (int nt = 0; nt < 4; nt++) {
            #pragma unroll
            for (int j = 0; j < 2; j++) {
                float v = mm[nt][j];
                v = fmaxf(v, __shfl_xor_sync(0xffffffffu, v, 4));
                v = fmaxf(v, __shfl_xor_sync(0xffffffffu, v, 8));
                v = fmaxf(v, __shfl_xor_sync(0xffffffffu, v, 16));
                mm[nt][j] = v;
            }
        }
        if (g == 0) {
            #pragma unroll
            for (int nt = 0; nt < 4; nt++) {
                int o0 = 8 * nt + 2 * t;
                gps[o0 * 32 + ml]       = mm[nt][0];
                gps[(o0 + 1) * 32 + ml] = mm[nt][1];
            }
        }
    }
    __syncthreads();   // gpool done; Bn/Tn/As dead

    // ============== k_out phase staging ==============
    float* w1T  = S + 2304;          // [68][32]
    float* w2T  = S + 4480;          // [32][32]
    float* na_s = S + 5504;          // [64]
    float* sb   = S + 5568;          // [4][32]
    int*   si   = (int*)(S + 5696);  // [4][32]
    float* hs   = S + 5824;          // [32][33]
    float* fuh2 = S + 6912;          // [32][33]
    float* o1s  = S + 2304;          // [64][33] over dead w1T

    for (int i = tid; i < 2176; i += 128) {
        int j = i >> 5, oo = i & 31;
        w1T[j * 32 + oo] = mlp_w1[oo * 68 + j];
    }
    for (int i = tid; i < 1024; i += 128) {
        int c = i >> 5, oo = i & 31;
        w2T[c * 32 + oo] = mlp_w2[oo * 32 + c];
    }
    if (tid < 64) {
        float s = 0.f;
        #pragma unroll
        for (int c = 0; c < 32; c++) { float v = xoT[tid * 36 + c]; s += v * v; }
        na_s[tid] = sqrtf(s);
    }

    const int ml = tid & 31, p = tid >> 5;
    const int m = mt * 32 + ml;

    float xl[32];
    #pragma unroll
    for (int c = 0; c < 32; c++)
        xl[c] = x_label[(size_t)b * 4096 + c * 128 + m];
    float nb = 0.f;
    #pragma unroll
    for (int c = 0; c < 32; c++) nb += xl[c] * xl[c];
    nb = sqrtf(nb);
    __syncthreads();

    // argmax (n split across 4 parts, first-max semantics preserved)
    float best = -3.4e38f; int bidx = 16 * p;
    #pragma unroll 1
    for (int n = 16 * p; n < 16 * p + 16; n++) {
        float num = 0.f;
        #pragma unroll
        for (int c = 0; c < 32; c++) num += xoT[n * 36 + c] * xl[c];
        float cs = num / fmaxf(na_s[n] * nb, 1e-8f);
        if (cs > best) { best = cs; bidx = n; }
    }
    sb[p * 32 + ml] = best; si[p * 32 + ml] = bidx;
    __syncthreads();
    best = sb[ml]; bidx = si[ml];
    #pragma unroll
    for (int pp = 1; pp < 4; pp++) {
        if (sb[pp * 32 + ml] > best) { best = sb[pp * 32 + ml]; bidx = si[pp * 32 + ml]; }
    }

    // MLP layer 1 (o in [8p, 8p+8))
    float hr[8];
    {
        const float* tx = template_xyz + (size_t)b * 192 + bidx * 3;
        float a0 = tx[0], a1 = tx[1], a2 = tx[2];
        #pragma unroll
        for (int oo = 0; oo < 8; oo++) {
            int oc = 8 * p + oo;
            hr[oo] = w1T[0 * 32 + oc] * best + w1T[1 * 32 + oc] * a0 +
                     w1T[2 * 32 + oc] * a1 + w1T[3 * 32 + oc] * a2;
        }
    }
    #pragma unroll
    for (int c = 0; c < 32; c++) {
        float xoc = xoT[bidx * 36 + c];
        #pragma unroll
        for (int oo = 0; oo < 8; oo++) hr[oo] += w1T[(4 + c) * 32 + 8 * p + oo] * xoc;
    }
    #pragma unroll
    for (int c = 0; c < 32; c++) {
        float v = xl[c];
        #pragma unroll
        for (int oo = 0; oo < 8; oo++) hr[oo] += w1T[(36 + c) * 32 + 8 * p + oo] * v;
    }
    #pragma unroll
    for (int oo = 0; oo < 8; oo++) {
        int oc = 8 * p + oo;
        hs[ml * 33 + oc] = fmaxf(mlp_s1[oc] * hr[oo] + mlp_t1[oc], 0.f);
    }
    __syncthreads();

    // MLP layer 2 -> fuh2
    float h2r[8] = {0.f, 0.f, 0.f, 0.f, 0.f, 0.f, 0.f, 0.f};
    #pragma unroll
    for (int c = 0; c < 32; c++) {
        float v = hs[ml * 33 + c];
        #pragma unroll
        for (int oo = 0; oo < 8; oo++) h2r[oo] += w2T[c * 32 + 8 * p + oo] * v;
    }
    #pragma unroll
    for (int oo = 0; oo < 8; oo++) {
        int oc = 8 * p + oo;
        fuh2[oc * 33 + ml] = fmaxf(mlp_s2[oc] * h2r[oo] + mlp_t2[oc], 0.f);
    }
    __syncthreads();

    // fl1 (o in [16p, 16p+16))
    float fv[64];
    #pragma unroll
    for (int c = 0; c < 32; c++) fv[c] = fuh2[c * 33 + ml];
    #pragma unroll
    for (int c = 0; c < 32; c++) fv[32 + c] = gps[c * 32 + ml];
    #pragma unroll 4
    for (int oo = 0; oo < 16; oo++) {
        int oc = 16 * p + oo;
        float acc = 0.f;
        const float4* wp4 = (const float4*)(fl_w1 + oc * 64);
        #pragma unroll
        for (int c4 = 0; c4 < 16; c4++) {
            float4 ww = __ldg(&wp4[c4]);
            acc += ww.x * fv[4 * c4] + ww.y * fv[4 * c4 + 1] +
                   ww.z * fv[4 * c4 + 2] + ww.w * fv[4 * c4 + 3];
        }
        o1s[oc * 33 + ml] = fmaxf(fl_s1[oc] * acc + fl_t1[oc], 0.f);
    }
    __syncthreads();

    // fl2
    float ov[64];
    #pragma unroll
    for (int c = 0; c < 64; c++) ov[c] = o1s[c * 33 + ml];
    #pragma unroll 4
    for (int oo = 0; oo < 16; oo++) {
        int oc = 16 * p + oo;
        float acc = fl_b2[oc];
        const float4* wp4 = (const float4*)(fl_w2 + oc * 64);
        #pragma unroll
        for (int c4 = 0; c4 < 16; c4++) {
            float4 ww = __ldg(&wp4[c4]);
            acc += ww.x * ov[4 * c4] + ww.y * ov[4 * c4 + 1] +
                   ww.z * ov[4 * c4 + 2] + ww.w * ov[4 * c4 + 3];
        }
        out[((size_t)b * 64 + oc) * NM + m] = acc;
    }
}

extern "C" void kernel_launch(void* const* d_in, const int* in_sizes, int n_in,
                              void* d_out, int out_size)
{
    const float* x_label      = (const float*)d_in[0];
    const float* x_object     = (const float*)d_in[1];
    const float* template_xyz = (const float*)d_in[2];
    const float* mlp_w1 = (const float*)d_in[3];
    const float* mlp_s1 = (const float*)d_in[4];
    const float* mlp_t1 = (const float*)d_in[5];
    const float* mlp_w2 = (const float*)d_in[6];
    const float* mlp_s2 = (const float*)d_in[7];
    const float* mlp_t2 = (const float*)d_in[8];
    const float* gw_w1  = (const float*)d_in[9];
    const float* gw_b1  = (const float*)d_in[10];
    const float* gw_s   = (const float*)d_in[11];
    const float* gw_t   = (const float*)d_in[12];
    const float* gw_w2  = (const float*)d_in[13];
    const float* gw_b2  = (const float*)d_in[14];
    const float* gm_w1  = (const float*)d_in[15];
    const float* gm_s1  = (const float*)d_in[16];
    const float* gm_t1  = (const float*)d_in[17];
    const float* gm_w2  = (const float*)d_in[18];
    const float* gm_s2  = (const float*)d_in[19];
    const float* gm_t2  = (const float*)d_in[20];
    const float* fl_w1  = (const float*)d_in[21];
    const float* fl_s1  = (const float*)d_in[22];
    const float* fl_t1  = (const float*)d_in[23];
    const float* fl_w2  = (const float*)d_in[24];
    const float* fl_b2  = (const float*)d_in[25];

    k_fused<<<512, 128>>>(x_label, x_object, template_xyz,
                          mlp_w1, mlp_s1, mlp_t1, mlp_w2, mlp_s2, mlp_t2,
                          gw_w1, gw_b1, gw_s, gw_t, gw_w2, gw_b2,
                          gm_w1, gm_s1, gm_t1, gm_w2, gm_s2, gm_t2,
                          fl_w1, fl_s1, fl_t1, fl_w2, fl_b2, (float*)d_out);
}